// round 4
// baseline (speedup 1.0000x reference)
#include <cuda_runtime.h>
#include <cuda_bf16.h>
#include <stdint.h>

// ---------------------------------------------------------------------------
// Problem dims
// ---------------------------------------------------------------------------
static const int cNS  = 8192;
static const int cNK  = 8192;
static const int cHID = 1024;
static const int cKED = 2048;
static const int CHUNKS = 8;   // softmax row chunks

// ---------------------------------------------------------------------------
// Scratch (__device__ globals; allocation-free)
// ---------------------------------------------------------------------------
__device__ __nv_bfloat16 g_Xs_h[(size_t)cNS * cHID];
__device__ __nv_bfloat16 g_Xs_l[(size_t)cNS * cHID];
__device__ __nv_bfloat16 g_Xk_h[(size_t)cNK * cKED];
__device__ __nv_bfloat16 g_Xk_l[(size_t)cNK * cKED];
__device__ __nv_bfloat16 g_Ws_h[(size_t)cHID * cHID];
__device__ __nv_bfloat16 g_Ws_l[(size_t)cHID * cHID];
__device__ __nv_bfloat16 g_Wk_h[(size_t)cHID * cKED];
__device__ __nv_bfloat16 g_Wk_l[(size_t)cHID * cKED];
__device__ __nv_bfloat16 g_S_h[(size_t)cNS * cHID];
__device__ __nv_bfloat16 g_S_l[(size_t)cNS * cHID];
__device__ __nv_bfloat16 g_K_h[(size_t)cNK * cHID];
__device__ __nv_bfloat16 g_K_l[(size_t)cNK * cHID];
__device__ __nv_bfloat16 g_VT_h[(size_t)cKED * cNK];   // V^T  [2048, 8192]
__device__ __nv_bfloat16 g_VT_l[(size_t)cKED * cNK];
__device__ __nv_bfloat16 g_At_h[(size_t)cNS * cNK];    // attns split planes
__device__ __nv_bfloat16 g_At_l[(size_t)cNS * cNK];
__device__ float g_pm[CHUNKS * cNK];
__device__ float g_ps[CHUNKS * cNK];
__device__ float g_m[cNK];
__device__ float g_rs[cNK];

// ---------------------------------------------------------------------------
// Helpers
// ---------------------------------------------------------------------------
__device__ __forceinline__ uint32_t smem_to_u32(const void* p) {
    uint32_t a;
    asm("{ .reg .u64 t; cvta.to.shared.u64 t, %1; cvt.u32.u64 %0, t; }"
        : "=r"(a) : "l"(p));
    return a;
}

__device__ __forceinline__ void cp_async16(uint32_t smem_addr, const void* gptr) {
    asm volatile("cp.async.cg.shared.global [%0], [%1], 16;\n"
                 :: "r"(smem_addr), "l"(__cvta_generic_to_global(gptr)));
}
__device__ __forceinline__ void cp_commit() {
    asm volatile("cp.async.commit_group;\n" ::: "memory");
}
template <int N>
__device__ __forceinline__ void cp_wait() {
    asm volatile("cp.async.wait_group %0;\n" :: "n"(N) : "memory");
}

__device__ __forceinline__ void ldsm_x4(uint32_t (&r)[4], uint32_t addr) {
    asm volatile("ldmatrix.sync.aligned.m8n8.x4.shared.b16 {%0,%1,%2,%3}, [%4];\n"
                 : "=r"(r[0]), "=r"(r[1]), "=r"(r[2]), "=r"(r[3]) : "r"(addr));
}

__device__ __forceinline__ void mma16816(float (&c)[4], const uint32_t (&a)[4],
                                         uint32_t b0, uint32_t b1) {
    asm volatile(
        "mma.sync.aligned.m16n8k16.row.col.f32.bf16.bf16.f32 "
        "{%0,%1,%2,%3}, {%4,%5,%6,%7}, {%8,%9}, {%0,%1,%2,%3};\n"
        : "+f"(c[0]), "+f"(c[1]), "+f"(c[2]), "+f"(c[3])
        : "r"(a[0]), "r"(a[1]), "r"(a[2]), "r"(a[3]), "r"(b0), "r"(b1));
}

__device__ __forceinline__ void split1(float x, __nv_bfloat16& h, __nv_bfloat16& l) {
    h = __float2bfloat16(x);
    l = __float2bfloat16(x - __bfloat162float(h));
}

// ---------------------------------------------------------------------------
// Split / transpose-split preprocessing
// ---------------------------------------------------------------------------
__global__ void split_kernel(const float* __restrict__ in,
                             __nv_bfloat16* __restrict__ hi,
                             __nv_bfloat16* __restrict__ lo, size_t n) {
    size_t i = ((size_t)blockIdx.x * 256 + threadIdx.x) * 4;
    if (i >= n) return;
    float4 v = *(const float4*)(in + i);
    __nv_bfloat16 h0, h1, h2, h3, l0, l1, l2, l3;
    split1(v.x, h0, l0); split1(v.y, h1, l1);
    split1(v.z, h2, l2); split1(v.w, h3, l3);
    *(__nv_bfloat162*)(hi + i)     = __nv_bfloat162(h0, h1);
    *(__nv_bfloat162*)(hi + i + 2) = __nv_bfloat162(h2, h3);
    *(__nv_bfloat162*)(lo + i)     = __nv_bfloat162(l0, l1);
    *(__nv_bfloat162*)(lo + i + 2) = __nv_bfloat162(l2, l3);
}

__global__ void transpose_split_kernel(const float* __restrict__ in,
                                       __nv_bfloat16* __restrict__ hi,
                                       __nv_bfloat16* __restrict__ lo,
                                       int R, int C) {
    __shared__ float t[32][33];
    int c0 = blockIdx.x * 32, r0 = blockIdx.y * 32;
    int tx = threadIdx.x, ty = threadIdx.y;
#pragma unroll
    for (int j = 0; j < 4; ++j)
        t[ty + j * 8][tx] = in[(size_t)(r0 + ty + j * 8) * C + c0 + tx];
    __syncthreads();
#pragma unroll
    for (int j = 0; j < 4; ++j) {
        float v = t[tx][ty + j * 8];
        __nv_bfloat16 h, l; split1(v, h, l);
        size_t off = (size_t)(c0 + ty + j * 8) * R + r0 + tx;
        hi[off] = h; lo[off] = l;
    }
}

// ---------------------------------------------------------------------------
// Split-bf16 HMMA GEMM: C[M,N] = (Ah+Al)[M,K] * (Bh+Bl)[N,K]^T (+ bias)
// 256x128 CTA tile, BK=32, 3-stage cp.async pipeline, 16 warps (4x4),
// warp tile 64x32, mma.sync m16n8k16 bf16, 3 passes (AhBh, AhBl, AlBh).
// SMEM rows padded to 80B -> conflict-free ldmatrix.
// ---------------------------------------------------------------------------
static const int ROWB    = 80;                 // 64B data + 16B pad
static const int TILE_A  = 256 * ROWB;         // 20480 B per A plane-tile
static const int TILE_BB = 128 * ROWB;         // 10240 B per B plane-tile
static const int STAGE_B = 2 * TILE_A + 2 * TILE_BB;   // 61440
static const int STAGES  = 3;
static const int SMEM_NEED = STAGES * STAGE_B; // 184320

template <bool BIAS, bool SPLIT>
__global__ __launch_bounds__(512, 1)
void mma_gemm(const __nv_bfloat16* __restrict__ Ah, const __nv_bfloat16* __restrict__ Al,
              const __nv_bfloat16* __restrict__ Bh, const __nv_bfloat16* __restrict__ Bl,
              const float* __restrict__ bias,
              float* __restrict__ C,
              __nv_bfloat16* __restrict__ Ch, __nv_bfloat16* __restrict__ Cl,
              int M, int N, int K)
{
    extern __shared__ char sm[];
    const uint32_t sbase = smem_to_u32(sm);

    const int tid = threadIdx.x;
    const int wid = tid >> 5, lane = tid & 31;
    const int wm = wid >> 2, wn = wid & 3;      // 4 x 4 warp grid
    const int row0 = blockIdx.y * 256, col0 = blockIdx.x * 128;

    const __nv_bfloat16* Ahb = Ah + (size_t)row0 * K;
    const __nv_bfloat16* Alb = Al + (size_t)row0 * K;
    const __nv_bfloat16* Bhb = Bh + (size_t)col0 * K;
    const __nv_bfloat16* Blb = Bl + (size_t)col0 * K;

    const int NT = K >> 5;   // k32 stages

    // ---- async load of one stage: 3072 x 16B chunks, 6 per thread.
    // unit = 64B row-quarter group; i=0,1 -> Ah, i=2,3 -> Al, i=4 -> Bh, i=5 -> Bl
    auto issue_loads = [&](int kt, int s) {
        const int k0 = kt << 5;
        const uint32_t sb = sbase + s * STAGE_B;
#pragma unroll
        for (int i = 0; i < 6; ++i) {
            int q = tid + i * 512;
            int unit = q >> 2, c = q & 3;
            const __nv_bfloat16* g;
            uint32_t d;
            if (i < 2) {            // Ah rows 0..255
                int row = unit;
                g = Ahb + (size_t)row * K + k0 + c * 8;
                d = sb + row * ROWB + c * 16;
            } else if (i < 4) {     // Al rows 0..255
                int row = unit - 256;
                g = Alb + (size_t)row * K + k0 + c * 8;
                d = sb + TILE_A + row * ROWB + c * 16;
            } else if (i < 5) {     // Bh rows 0..127
                int row = unit - 512;
                g = Bhb + (size_t)row * K + k0 + c * 8;
                d = sb + 2 * TILE_A + row * ROWB + c * 16;
            } else {                // Bl rows 0..127
                int row = unit - 640;
                g = Blb + (size_t)row * K + k0 + c * 8;
                d = sb + 2 * TILE_A + TILE_BB + row * ROWB + c * 16;
            }
            cp_async16(d, g);
        }
    };

    issue_loads(0, 0); cp_commit();
    issue_loads(1, 1); cp_commit();

    float acc[4][4][4];
#pragma unroll
    for (int i = 0; i < 4; ++i)
#pragma unroll
        for (int j = 0; j < 4; ++j)
#pragma unroll
            for (int v = 0; v < 4; ++v) acc[i][j][v] = 0.f;

    const int lrow = lane & 15, lcol = lane >> 4;

    for (int kt = 0; kt < NT; ++kt) {
        const int s = kt % 3;
        cp_wait<1>();
        __syncthreads();
        if (kt + 2 < NT) issue_loads(kt + 2, (kt + 2) % 3);
        cp_commit();

#pragma unroll
        for (int ks = 0; ks < 2; ++ks) {
            uint32_t ah[4][4], al[4][4], bh[2][4], bl[2][4];
            const uint32_t abase = sbase + s * STAGE_B
                + (wm * 64 + lrow) * ROWB + ks * 32 + lcol * 16;
#pragma unroll
            for (int mi = 0; mi < 4; ++mi) {
                ldsm_x4(ah[mi], abase + mi * 16 * ROWB);
                ldsm_x4(al[mi], abase + mi * 16 * ROWB + TILE_A);
            }
            const uint32_t bbase = sbase + s * STAGE_B + 2 * TILE_A
                + (wn * 32 + lrow) * ROWB + ks * 32 + lcol * 16;
#pragma unroll
            for (int bj = 0; bj < 2; ++bj) {
                ldsm_x4(bh[bj], bbase + bj * 16 * ROWB);
                ldsm_x4(bl[bj], bbase + bj * 16 * ROWB + TILE_BB);
            }
#pragma unroll
            for (int mi = 0; mi < 4; ++mi) {
#pragma unroll
                for (int jn = 0; jn < 4; ++jn) {
                    const int bj = jn >> 1, hf = jn & 1;
                    mma16816(acc[mi][jn], ah[mi], bh[bj][hf], bh[bj][hf + 2]);
                    mma16816(acc[mi][jn], ah[mi], bl[bj][hf], bl[bj][hf + 2]);
                    mma16816(acc[mi][jn], al[mi], bh[bj][hf], bh[bj][hf + 2]);
                }
            }
        }
    }

    // ---- epilogue ----
    const int g = lane >> 2, cq = (lane & 3) * 2;
#pragma unroll
    for (int mi = 0; mi < 4; ++mi) {
#pragma unroll
        for (int jn = 0; jn < 4; ++jn) {
            const int r0w = row0 + wm * 64 + mi * 16 + g;
            const int cc = col0 + wn * 32 + jn * 8 + cq;
            float v0 = acc[mi][jn][0], v1 = acc[mi][jn][1];
            float v2 = acc[mi][jn][2], v3 = acc[mi][jn][3];
            if (BIAS) {
                float b0 = bias[cc], b1 = bias[cc + 1];
                v0 += b0; v1 += b1; v2 += b0; v3 += b1;
            }
            if (SPLIT) {
                __nv_bfloat16 h0, h1, h2, h3, l0, l1, l2, l3;
                split1(v0, h0, l0); split1(v1, h1, l1);
                split1(v2, h2, l2); split1(v3, h3, l3);
                size_t o0 = (size_t)r0w * N + cc;
                size_t o1 = (size_t)(r0w + 8) * N + cc;
                *(__nv_bfloat162*)(Ch + o0) = __nv_bfloat162(h0, h1);
                *(__nv_bfloat162*)(Cl + o0) = __nv_bfloat162(l0, l1);
                *(__nv_bfloat162*)(Ch + o1) = __nv_bfloat162(h2, h3);
                *(__nv_bfloat162*)(Cl + o1) = __nv_bfloat162(l2, l3);
            } else {
                *(float2*)(C + (size_t)r0w * N + cc)       = make_float2(v0, v1);
                *(float2*)(C + (size_t)(r0w + 8) * N + cc) = make_float2(v2, v3);
            }
        }
    }
}

// ---------------------------------------------------------------------------
// Column softmax (axis 0) on scores [Ns, Nk]
// ---------------------------------------------------------------------------
__global__ void softmax_pass1(const float* __restrict__ sc) {
    const int j4 = (blockIdx.x * 256 + threadIdx.x) * 4;
    const int chunk = blockIdx.y;
    const int rows = cNS / CHUNKS;
    const size_t i0 = (size_t)chunk * rows;
    float m0 = -1e30f, m1 = -1e30f, m2 = -1e30f, m3 = -1e30f;
    float s0 = 0.f, s1 = 0.f, s2 = 0.f, s3 = 0.f;
#pragma unroll 4
    for (int i = 0; i < rows; ++i) {
        float4 x = *(const float4*)(sc + (i0 + i) * cNK + j4);
        float n0 = fmaxf(m0, x.x); s0 = s0 * __expf(m0 - n0) + __expf(x.x - n0); m0 = n0;
        float n1 = fmaxf(m1, x.y); s1 = s1 * __expf(m1 - n1) + __expf(x.y - n1); m1 = n1;
        float n2 = fmaxf(m2, x.z); s2 = s2 * __expf(m2 - n2) + __expf(x.z - n2); m2 = n2;
        float n3 = fmaxf(m3, x.w); s3 = s3 * __expf(m3 - n3) + __expf(x.w - n3); m3 = n3;
    }
    g_pm[chunk * cNK + j4 + 0] = m0; g_ps[chunk * cNK + j4 + 0] = s0;
    g_pm[chunk * cNK + j4 + 1] = m1; g_ps[chunk * cNK + j4 + 1] = s1;
    g_pm[chunk * cNK + j4 + 2] = m2; g_ps[chunk * cNK + j4 + 2] = s2;
    g_pm[chunk * cNK + j4 + 3] = m3; g_ps[chunk * cNK + j4 + 3] = s3;
}

__global__ void softmax_pass2() {
    const int j = blockIdx.x * 256 + threadIdx.x;
    float m = -1e30f, s = 0.f;
#pragma unroll
    for (int c = 0; c < CHUNKS; ++c) {
        float pm = g_pm[c * cNK + j];
        float ps = g_ps[c * cNK + j];
        float nm = fmaxf(m, pm);
        s = s * __expf(m - nm) + ps * __expf(pm - nm);
        m = nm;
    }
    g_m[j] = m;
    g_rs[j] = 1.f / s;
}

__global__ void softmax_pass3(float* __restrict__ sc,
                              __nv_bfloat16* __restrict__ hi,
                              __nv_bfloat16* __restrict__ lo) {
    const int j4 = (blockIdx.x * 256 + threadIdx.x) * 4;
    const size_t i = blockIdx.y;
    float4 x = *(float4*)(sc + i * cNK + j4);
    float4 m = *(const float4*)(&g_m[j4]);
    float4 rs = *(const float4*)(&g_rs[j4]);
    x.x = __expf(x.x - m.x) * rs.x;
    x.y = __expf(x.y - m.y) * rs.y;
    x.z = __expf(x.z - m.z) * rs.z;
    x.w = __expf(x.w - m.w) * rs.w;
    *(float4*)(sc + i * cNK + j4) = x;
    __nv_bfloat16 h0, h1, h2, h3, l0, l1, l2, l3;
    split1(x.x, h0, l0); split1(x.y, h1, l1);
    split1(x.z, h2, l2); split1(x.w, h3, l3);
    size_t off = i * cNK + j4;
    *(__nv_bfloat162*)(hi + off)     = __nv_bfloat162(h0, h1);
    *(__nv_bfloat162*)(hi + off + 2) = __nv_bfloat162(h2, h3);
    *(__nv_bfloat162*)(lo + off)     = __nv_bfloat162(l0, l1);
    *(__nv_bfloat162*)(lo + off + 2) = __nv_bfloat162(l2, l3);
}

// ---------------------------------------------------------------------------
// Launch
// ---------------------------------------------------------------------------
extern "C" void kernel_launch(void* const* d_in, const int* in_sizes, int n_in,
                              void* d_out, int out_size)
{
    const float* Xs = (const float*)d_in[0];
    const float* Xk = (const float*)d_in[1];
    const float* Ws = (const float*)d_in[2];
    const float* bs = (const float*)d_in[3];
    const float* Wk = (const float*)d_in[4];
    const float* bk = (const float*)d_in[5];

    float* attns = (float*)d_out;
    float* fused = attns + (size_t)cNS * cNK;

    __nv_bfloat16 *Xsh, *Xsl, *Xkh, *Xkl, *Wsh, *Wsl, *Wkh, *Wkl;
    __nv_bfloat16 *Sh, *Sl, *Kh, *Kl, *VTh, *VTl, *Ath, *Atl;
    cudaGetSymbolAddress((void**)&Xsh, g_Xs_h); cudaGetSymbolAddress((void**)&Xsl, g_Xs_l);
    cudaGetSymbolAddress((void**)&Xkh, g_Xk_h); cudaGetSymbolAddress((void**)&Xkl, g_Xk_l);
    cudaGetSymbolAddress((void**)&Wsh, g_Ws_h); cudaGetSymbolAddress((void**)&Wsl, g_Ws_l);
    cudaGetSymbolAddress((void**)&Wkh, g_Wk_h); cudaGetSymbolAddress((void**)&Wkl, g_Wk_l);
    cudaGetSymbolAddress((void**)&Sh,  g_S_h);  cudaGetSymbolAddress((void**)&Sl,  g_S_l);
    cudaGetSymbolAddress((void**)&Kh,  g_K_h);  cudaGetSymbolAddress((void**)&Kl,  g_K_l);
    cudaGetSymbolAddress((void**)&VTh, g_VT_h); cudaGetSymbolAddress((void**)&VTl, g_VT_l);
    cudaGetSymbolAddress((void**)&Ath, g_At_h); cudaGetSymbolAddress((void**)&Atl, g_At_l);

    cudaFuncSetAttribute(mma_gemm<true, true>,
                         cudaFuncAttributeMaxDynamicSharedMemorySize, SMEM_NEED);
    cudaFuncSetAttribute(mma_gemm<false, false>,
                         cudaFuncAttributeMaxDynamicSharedMemorySize, SMEM_NEED);

    // Split inputs
    {
        size_t n;
        n = (size_t)cNS * cHID; split_kernel<<<(unsigned)(n / 1024), 256>>>(Xs, Xsh, Xsl, n);
        n = (size_t)cNK * cKED; split_kernel<<<(unsigned)(n / 1024), 256>>>(Xk, Xkh, Xkl, n);
        n = (size_t)cHID * cHID; split_kernel<<<(unsigned)(n / 1024), 256>>>(Ws, Wsh, Wsl, n);
        n = (size_t)cHID * cKED; split_kernel<<<(unsigned)(n / 1024), 256>>>(Wk, Wkh, Wkl, n);
    }
    // V^T split
    transpose_split_kernel<<<dim3(cKED / 32, cNK / 32), dim3(32, 8)>>>(
        Xk, VTh, VTl, cNK, cKED);

    // S = Xs @ Ws^T + bs  -> split planes  [8192, 1024]
    mma_gemm<true, true><<<dim3(cHID / 128, cNS / 256), 512, SMEM_NEED>>>(
        Xsh, Xsl, Wsh, Wsl, bs, nullptr, Sh, Sl, cNS, cHID, cHID);

    // K = Xk @ Wk^T + bk  -> split planes  [8192, 1024]
    mma_gemm<true, true><<<dim3(cHID / 128, cNK / 256), 512, SMEM_NEED>>>(
        Xkh, Xkl, Wkh, Wkl, bk, nullptr, Kh, Kl, cNK, cHID, cKED);

    // scores = S @ K^T -> fp32 into attns region  [8192, 8192]
    mma_gemm<false, false><<<dim3(cNK / 128, cNS / 256), 512, SMEM_NEED>>>(
        Sh, Sl, Kh, Kl, nullptr, attns, nullptr, nullptr, cNS, cNK, cHID);

    // softmax over axis 0, in place; emit split planes
    softmax_pass1<<<dim3(cNK / 1024, CHUNKS), 256>>>(attns);
    softmax_pass2<<<cNK / 256, 256>>>();
    softmax_pass3<<<dim3(cNK / 1024, cNS), 256>>>(attns, Ath, Atl);

    // fused = attns @ V = attns @ (V^T)^T  [8192, 2048]
    mma_gemm<false, false><<<dim3(cKED / 128, cNS / 256), 512, SMEM_NEED>>>(
        Ath, Atl, VTh, VTl, nullptr, fused, nullptr, nullptr, cNS, cKED, cNK);
}

// round 5
// speedup vs baseline: 1.2688x; 1.2688x over previous
#include <cuda_runtime.h>
#include <cuda_bf16.h>
#include <cuda_fp16.h>
#include <stdint.h>

// ---------------------------------------------------------------------------
// Problem dims
// ---------------------------------------------------------------------------
static const int cNS  = 8192;
static const int cNK  = 8192;
static const int cHID = 1024;
static const int cKED = 2048;
static const int CHUNKS = 8;   // softmax row chunks

// ---------------------------------------------------------------------------
// Scratch (__device__ globals; allocation-free)
// ---------------------------------------------------------------------------
__device__ __nv_bfloat16 g_Xs_h[(size_t)cNS * cHID];
__device__ __nv_bfloat16 g_Xs_l[(size_t)cNS * cHID];
__device__ __nv_bfloat16 g_Xk_h[(size_t)cNK * cKED];
__device__ __nv_bfloat16 g_Xk_l[(size_t)cNK * cKED];
__device__ __nv_bfloat16 g_Ws_h[(size_t)cHID * cHID];
__device__ __nv_bfloat16 g_Ws_l[(size_t)cHID * cHID];
__device__ __nv_bfloat16 g_Wk_h[(size_t)cHID * cKED];
__device__ __nv_bfloat16 g_Wk_l[(size_t)cHID * cKED];
__device__ __nv_bfloat16 g_S_h[(size_t)cNS * cHID];
__device__ __nv_bfloat16 g_S_l[(size_t)cNS * cHID];
__device__ __nv_bfloat16 g_K_h[(size_t)cNK * cHID];
__device__ __nv_bfloat16 g_K_l[(size_t)cNK * cHID];
__device__ __half g_VT[(size_t)cKED * cNK];            // V^T fp16 [2048, 8192]
__device__ __half g_At_h[(size_t)cNS * cNK];           // attns fp16 hi
__device__ __half g_At_l[(size_t)cNS * cNK];           // attns fp16 lo
__device__ float g_pm[CHUNKS * cNK];
__device__ float g_ps[CHUNKS * cNK];
__device__ float g_m[cNK];
__device__ float g_rs[cNK];

// ---------------------------------------------------------------------------
// Helpers
// ---------------------------------------------------------------------------
__device__ __forceinline__ uint32_t smem_to_u32(const void* p) {
    uint32_t a;
    asm("{ .reg .u64 t; cvta.to.shared.u64 t, %1; cvt.u32.u64 %0, t; }"
        : "=r"(a) : "l"(p));
    return a;
}

__device__ __forceinline__ void cp_async16(uint32_t smem_addr, const void* gptr) {
    asm volatile("cp.async.cg.shared.global [%0], [%1], 16;\n"
                 :: "r"(smem_addr), "l"(__cvta_generic_to_global(gptr)));
}
__device__ __forceinline__ void cp_commit() {
    asm volatile("cp.async.commit_group;\n" ::: "memory");
}
template <int N>
__device__ __forceinline__ void cp_wait() {
    asm volatile("cp.async.wait_group %0;\n" :: "n"(N) : "memory");
}

__device__ __forceinline__ void ldsm_x4(uint32_t (&r)[4], uint32_t addr) {
    asm volatile("ldmatrix.sync.aligned.m8n8.x4.shared.b16 {%0,%1,%2,%3}, [%4];\n"
                 : "=r"(r[0]), "=r"(r[1]), "=r"(r[2]), "=r"(r[3]) : "r"(addr));
}

__device__ __forceinline__ void mma16816(float (&c)[4], const uint32_t (&a)[4],
                                         uint32_t b0, uint32_t b1) {
    asm volatile(
        "mma.sync.aligned.m16n8k16.row.col.f32.bf16.bf16.f32 "
        "{%0,%1,%2,%3}, {%4,%5,%6,%7}, {%8,%9}, {%0,%1,%2,%3};\n"
        : "+f"(c[0]), "+f"(c[1]), "+f"(c[2]), "+f"(c[3])
        : "r"(a[0]), "r"(a[1]), "r"(a[2]), "r"(a[3]), "r"(b0), "r"(b1));
}

__device__ __forceinline__ void mma16816h(float (&c)[4], const uint32_t (&a)[4],
                                          uint32_t b0, uint32_t b1) {
    asm volatile(
        "mma.sync.aligned.m16n8k16.row.col.f32.f16.f16.f32 "
        "{%0,%1,%2,%3}, {%4,%5,%6,%7}, {%8,%9}, {%0,%1,%2,%3};\n"
        : "+f"(c[0]), "+f"(c[1]), "+f"(c[2]), "+f"(c[3])
        : "r"(a[0]), "r"(a[1]), "r"(a[2]), "r"(a[3]), "r"(b0), "r"(b1));
}

__device__ __forceinline__ void split1(float x, __nv_bfloat16& h, __nv_bfloat16& l) {
    h = __float2bfloat16(x);
    l = __float2bfloat16(x - __bfloat162float(h));
}
__device__ __forceinline__ void split1h(float x, __half& h, __half& l) {
    h = __float2half(x);
    l = __float2half(x - __half2float(h));
}

// ---------------------------------------------------------------------------
// Split / transpose preprocessing
// ---------------------------------------------------------------------------
__global__ void split_kernel(const float* __restrict__ in,
                             __nv_bfloat16* __restrict__ hi,
                             __nv_bfloat16* __restrict__ lo, size_t n) {
    size_t i = ((size_t)blockIdx.x * 256 + threadIdx.x) * 4;
    if (i >= n) return;
    float4 v = *(const float4*)(in + i);
    __nv_bfloat16 h0, h1, h2, h3, l0, l1, l2, l3;
    split1(v.x, h0, l0); split1(v.y, h1, l1);
    split1(v.z, h2, l2); split1(v.w, h3, l3);
    *(__nv_bfloat162*)(hi + i)     = __nv_bfloat162(h0, h1);
    *(__nv_bfloat162*)(hi + i + 2) = __nv_bfloat162(h2, h3);
    *(__nv_bfloat162*)(lo + i)     = __nv_bfloat162(l0, l1);
    *(__nv_bfloat162*)(lo + i + 2) = __nv_bfloat162(l2, l3);
}

// Transpose fp32 [R, C] -> fp16 [C, R]
__global__ void transpose_half_kernel(const float* __restrict__ in,
                                      __half* __restrict__ out,
                                      int R, int C) {
    __shared__ float t[32][33];
    int c0 = blockIdx.x * 32, r0 = blockIdx.y * 32;
    int tx = threadIdx.x, ty = threadIdx.y;
#pragma unroll
    for (int j = 0; j < 4; ++j)
        t[ty + j * 8][tx] = in[(size_t)(r0 + ty + j * 8) * C + c0 + tx];
    __syncthreads();
#pragma unroll
    for (int j = 0; j < 4; ++j) {
        float v = t[tx][ty + j * 8];
        out[(size_t)(c0 + ty + j * 8) * R + r0 + tx] = __float2half(v);
    }
}

// ---------------------------------------------------------------------------
// Common GEMM geometry (R3-proven): 128x128 CTA tile, BK=32, 3-stage
// cp.async pipeline, 8 warps (2x4), warp tile 64x32, 80B-padded SMEM rows.
// ---------------------------------------------------------------------------
static const int ROWB    = 80;                 // 64B data + 16B pad
static const int TILE_B  = 128 * ROWB;         // 10240 B per plane-tile

// === 3-pass split-bf16 GEMM: C = (Ah+Al) * (Bh+Bl)^T (+bias) ===
static const int STAGE_B3 = 4 * TILE_B;        // Ah, Al, Bh, Bl
static const int SMEM_3P  = 3 * STAGE_B3;      // 122880

template <bool BIAS, bool SPLIT>
__global__ __launch_bounds__(256, 1)
void mma_gemm(const __nv_bfloat16* __restrict__ Ah, const __nv_bfloat16* __restrict__ Al,
              const __nv_bfloat16* __restrict__ Bh, const __nv_bfloat16* __restrict__ Bl,
              const float* __restrict__ bias,
              float* __restrict__ C,
              __nv_bfloat16* __restrict__ Ch, __nv_bfloat16* __restrict__ Cl,
              int M, int N, int K)
{
    extern __shared__ char sm[];
    const uint32_t sbase = smem_to_u32(sm);

    const int tid = threadIdx.x;
    const int wid = tid >> 5, lane = tid & 31;
    const int wm = wid >> 2, wn = wid & 3;      // 2 x 4 warp grid
    const int row0 = blockIdx.y * 128, col0 = blockIdx.x * 128;

    const __nv_bfloat16* srcs[4] = {
        Ah + (size_t)row0 * K, Al + (size_t)row0 * K,
        Bh + (size_t)col0 * K, Bl + (size_t)col0 * K };

    const int NT = K >> 5;

    auto issue_loads = [&](int kt, int s) {
        const int k0 = kt << 5;
#pragma unroll
        for (int i = 0; i < 8; ++i) {
            int q = tid + i * 256;
            int t = q >> 9, idx = q & 511;
            int row = idx >> 2, c = idx & 3;
            const __nv_bfloat16* g = srcs[t] + (size_t)row * K + k0 + c * 8;
            uint32_t d = sbase + s * STAGE_B3 + t * TILE_B + row * ROWB + c * 16;
            cp_async16(d, g);
        }
    };

    issue_loads(0, 0); cp_commit();
    issue_loads(1, 1); cp_commit();

    float acc[4][4][4];
#pragma unroll
    for (int i = 0; i < 4; ++i)
#pragma unroll
        for (int j = 0; j < 4; ++j)
#pragma unroll
            for (int v = 0; v < 4; ++v) acc[i][j][v] = 0.f;

    const int lrow = lane & 15, lcol = lane >> 4;

    for (int kt = 0; kt < NT; ++kt) {
        const int s = kt % 3;
        cp_wait<1>();
        __syncthreads();
        if (kt + 2 < NT) issue_loads(kt + 2, (kt + 2) % 3);
        cp_commit();

#pragma unroll
        for (int ks = 0; ks < 2; ++ks) {
            uint32_t ah[4][4], al[4][4], bh[2][4], bl[2][4];
            const uint32_t abase = sbase + s * STAGE_B3
                + (wm * 64 + lrow) * ROWB + ks * 32 + lcol * 16;
#pragma unroll
            for (int mi = 0; mi < 4; ++mi) {
                ldsm_x4(ah[mi], abase + mi * 16 * ROWB);
                ldsm_x4(al[mi], abase + mi * 16 * ROWB + TILE_B);
            }
            const uint32_t bbase = sbase + s * STAGE_B3 + 2 * TILE_B
                + (wn * 32 + lrow) * ROWB + ks * 32 + lcol * 16;
#pragma unroll
            for (int bj = 0; bj < 2; ++bj) {
                ldsm_x4(bh[bj], bbase + bj * 16 * ROWB);
                ldsm_x4(bl[bj], bbase + bj * 16 * ROWB + TILE_B);
            }
#pragma unroll
            for (int mi = 0; mi < 4; ++mi) {
#pragma unroll
                for (int jn = 0; jn < 4; ++jn) {
                    const int bj = jn >> 1, hf = jn & 1;
                    mma16816(acc[mi][jn], ah[mi], bh[bj][hf], bh[bj][hf + 2]);
                    mma16816(acc[mi][jn], ah[mi], bl[bj][hf], bl[bj][hf + 2]);
                    mma16816(acc[mi][jn], al[mi], bh[bj][hf], bh[bj][hf + 2]);
                }
            }
        }
    }

    const int g = lane >> 2, cq = (lane & 3) * 2;
#pragma unroll
    for (int mi = 0; mi < 4; ++mi) {
#pragma unroll
        for (int jn = 0; jn < 4; ++jn) {
            const int r0w = row0 + wm * 64 + mi * 16 + g;
            const int cc = col0 + wn * 32 + jn * 8 + cq;
            float v0 = acc[mi][jn][0], v1 = acc[mi][jn][1];
            float v2 = acc[mi][jn][2], v3 = acc[mi][jn][3];
            if (BIAS) {
                float b0 = bias[cc], b1 = bias[cc + 1];
                v0 += b0; v1 += b1; v2 += b0; v3 += b1;
            }
            if (SPLIT) {
                __nv_bfloat16 h0, h1, h2, h3, l0, l1, l2, l3;
                split1(v0, h0, l0); split1(v1, h1, l1);
                split1(v2, h2, l2); split1(v3, h3, l3);
                size_t o0 = (size_t)r0w * N + cc;
                size_t o1 = (size_t)(r0w + 8) * N + cc;
                *(__nv_bfloat162*)(Ch + o0) = __nv_bfloat162(h0, h1);
                *(__nv_bfloat162*)(Cl + o0) = __nv_bfloat162(l0, l1);
                *(__nv_bfloat162*)(Ch + o1) = __nv_bfloat162(h2, h3);
                *(__nv_bfloat162*)(Cl + o1) = __nv_bfloat162(l2, l3);
            } else {
                *(float2*)(C + (size_t)r0w * N + cc)       = make_float2(v0, v1);
                *(float2*)(C + (size_t)(r0w + 8) * N + cc) = make_float2(v2, v3);
            }
        }
    }
}

// === 2-pass fp16 GEMM: C = (Ah+Al) * B^T, fp32 accumulate ===
static const int STAGE_B2 = 3 * TILE_B;        // Ah, Al, B
static const int SMEM_2P  = 3 * STAGE_B2;      // 92160

__global__ __launch_bounds__(256, 1)
void mma_gemm_f16(const __half* __restrict__ Ah, const __half* __restrict__ Al,
                  const __half* __restrict__ B,
                  float* __restrict__ C, int M, int N, int K)
{
    extern __shared__ char sm[];
    const uint32_t sbase = smem_to_u32(sm);

    const int tid = threadIdx.x;
    const int wid = tid >> 5, lane = tid & 31;
    const int wm = wid >> 2, wn = wid & 3;
    const int row0 = blockIdx.y * 128, col0 = blockIdx.x * 128;

    const __half* srcs[3] = {
        Ah + (size_t)row0 * K, Al + (size_t)row0 * K, B + (size_t)col0 * K };

    const int NT = K >> 5;

    auto issue_loads = [&](int kt, int s) {
        const int k0 = kt << 5;
#pragma unroll
        for (int i = 0; i < 6; ++i) {
            int q = tid + i * 256;
            int t = q >> 9, idx = q & 511;
            int row = idx >> 2, c = idx & 3;
            const __half* g = srcs[t] + (size_t)row * K + k0 + c * 8;
            uint32_t d = sbase + s * STAGE_B2 + t * TILE_B + row * ROWB + c * 16;
            cp_async16(d, g);
        }
    };

    issue_loads(0, 0); cp_commit();
    issue_loads(1, 1); cp_commit();

    float acc[4][4][4];
#pragma unroll
    for (int i = 0; i < 4; ++i)
#pragma unroll
        for (int j = 0; j < 4; ++j)
#pragma unroll
            for (int v = 0; v < 4; ++v) acc[i][j][v] = 0.f;

    const int lrow = lane & 15, lcol = lane >> 4;

    for (int kt = 0; kt < NT; ++kt) {
        const int s = kt % 3;
        cp_wait<1>();
        __syncthreads();
        if (kt + 2 < NT) issue_loads(kt + 2, (kt + 2) % 3);
        cp_commit();

#pragma unroll
        for (int ks = 0; ks < 2; ++ks) {
            uint32_t ah[4][4], al[4][4], bb[2][4];
            const uint32_t abase = sbase + s * STAGE_B2
                + (wm * 64 + lrow) * ROWB + ks * 32 + lcol * 16;
#pragma unroll
            for (int mi = 0; mi < 4; ++mi) {
                ldsm_x4(ah[mi], abase + mi * 16 * ROWB);
                ldsm_x4(al[mi], abase + mi * 16 * ROWB + TILE_B);
            }
            const uint32_t bbase = sbase + s * STAGE_B2 + 2 * TILE_B
                + (wn * 32 + lrow) * ROWB + ks * 32 + lcol * 16;
#pragma unroll
            for (int bj = 0; bj < 2; ++bj)
                ldsm_x4(bb[bj], bbase + bj * 16 * ROWB);
#pragma unroll
            for (int mi = 0; mi < 4; ++mi) {
#pragma unroll
                for (int jn = 0; jn < 4; ++jn) {
                    const int bj = jn >> 1, hf = jn & 1;
                    mma16816h(acc[mi][jn], ah[mi], bb[bj][hf], bb[bj][hf + 2]);
                    mma16816h(acc[mi][jn], al[mi], bb[bj][hf], bb[bj][hf + 2]);
                }
            }
        }
    }

    const int g = lane >> 2, cq = (lane & 3) * 2;
#pragma unroll
    for (int mi = 0; mi < 4; ++mi) {
#pragma unroll
        for (int jn = 0; jn < 4; ++jn) {
            const int r0w = row0 + wm * 64 + mi * 16 + g;
            const int cc = col0 + wn * 32 + jn * 8 + cq;
            *(float2*)(C + (size_t)r0w * N + cc)
                = make_float2(acc[mi][jn][0], acc[mi][jn][1]);
            *(float2*)(C + (size_t)(r0w + 8) * N + cc)
                = make_float2(acc[mi][jn][2], acc[mi][jn][3]);
        }
    }
}

// ---------------------------------------------------------------------------
// Column softmax (axis 0) on scores [Ns, Nk]
// ---------------------------------------------------------------------------
__global__ void softmax_pass1(const float* __restrict__ sc) {
    const int j4 = (blockIdx.x * 256 + threadIdx.x) * 4;
    const int chunk = blockIdx.y;
    const int rows = cNS / CHUNKS;
    const size_t i0 = (size_t)chunk * rows;
    float m0 = -1e30f, m1 = -1e30f, m2 = -1e30f, m3 = -1e30f;
    float s0 = 0.f, s1 = 0.f, s2 = 0.f, s3 = 0.f;
#pragma unroll 4
    for (int i = 0; i < rows; ++i) {
        float4 x = *(const float4*)(sc + (i0 + i) * cNK + j4);
        float n0 = fmaxf(m0, x.x); s0 = s0 * __expf(m0 - n0) + __expf(x.x - n0); m0 = n0;
        float n1 = fmaxf(m1, x.y); s1 = s1 * __expf(m1 - n1) + __expf(x.y - n1); m1 = n1;
        float n2 = fmaxf(m2, x.z); s2 = s2 * __expf(m2 - n2) + __expf(x.z - n2); m2 = n2;
        float n3 = fmaxf(m3, x.w); s3 = s3 * __expf(m3 - n3) + __expf(x.w - n3); m3 = n3;
    }
    g_pm[chunk * cNK + j4 + 0] = m0; g_ps[chunk * cNK + j4 + 0] = s0;
    g_pm[chunk * cNK + j4 + 1] = m1; g_ps[chunk * cNK + j4 + 1] = s1;
    g_pm[chunk * cNK + j4 + 2] = m2; g_ps[chunk * cNK + j4 + 2] = s2;
    g_pm[chunk * cNK + j4 + 3] = m3; g_ps[chunk * cNK + j4 + 3] = s3;
}

__global__ void softmax_pass2() {
    const int j = blockIdx.x * 256 + threadIdx.x;
    float m = -1e30f, s = 0.f;
#pragma unroll
    for (int c = 0; c < CHUNKS; ++c) {
        float pm = g_pm[c * cNK + j];
        float ps = g_ps[c * cNK + j];
        float nm = fmaxf(m, pm);
        s = s * __expf(m - nm) + ps * __expf(pm - nm);
        m = nm;
    }
    g_m[j] = m;
    g_rs[j] = 1.f / s;
}

// Normalize in place + emit fp16 split planes for the fused GEMM.
__global__ void softmax_pass3(float* __restrict__ sc,
                              __half* __restrict__ hi,
                              __half* __restrict__ lo) {
    const int j4 = (blockIdx.x * 256 + threadIdx.x) * 4;
    const size_t i = blockIdx.y;
    float4 x = *(float4*)(sc + i * cNK + j4);
    float4 m = *(const float4*)(&g_m[j4]);
    float4 rs = *(const float4*)(&g_rs[j4]);
    x.x = __expf(x.x - m.x) * rs.x;
    x.y = __expf(x.y - m.y) * rs.y;
    x.z = __expf(x.z - m.z) * rs.z;
    x.w = __expf(x.w - m.w) * rs.w;
    *(float4*)(sc + i * cNK + j4) = x;
    __half h0, h1, h2, h3, l0, l1, l2, l3;
    split1h(x.x, h0, l0); split1h(x.y, h1, l1);
    split1h(x.z, h2, l2); split1h(x.w, h3, l3);
    size_t off = i * cNK + j4;
    *(__half2*)(hi + off)     = __half2(h0, h1);
    *(__half2*)(hi + off + 2) = __half2(h2, h3);
    *(__half2*)(lo + off)     = __half2(l0, l1);
    *(__half2*)(lo + off + 2) = __half2(l2, l3);
}

// ---------------------------------------------------------------------------
// Launch
// ---------------------------------------------------------------------------
extern "C" void kernel_launch(void* const* d_in, const int* in_sizes, int n_in,
                              void* d_out, int out_size)
{
    const float* Xs = (const float*)d_in[0];
    const float* Xk = (const float*)d_in[1];
    const float* Ws = (const float*)d_in[2];
    const float* bs = (const float*)d_in[3];
    const float* Wk = (const float*)d_in[4];
    const float* bk = (const float*)d_in[5];

    float* attns = (float*)d_out;
    float* fused = attns + (size_t)cNS * cNK;

    __nv_bfloat16 *Xsh, *Xsl, *Xkh, *Xkl, *Wsh, *Wsl, *Wkh, *Wkl;
    __nv_bfloat16 *Sh, *Sl, *Kh, *Kl;
    __half *VT, *Ath, *Atl;
    cudaGetSymbolAddress((void**)&Xsh, g_Xs_h); cudaGetSymbolAddress((void**)&Xsl, g_Xs_l);
    cudaGetSymbolAddress((void**)&Xkh, g_Xk_h); cudaGetSymbolAddress((void**)&Xkl, g_Xk_l);
    cudaGetSymbolAddress((void**)&Wsh, g_Ws_h); cudaGetSymbolAddress((void**)&Wsl, g_Ws_l);
    cudaGetSymbolAddress((void**)&Wkh, g_Wk_h); cudaGetSymbolAddress((void**)&Wkl, g_Wk_l);
    cudaGetSymbolAddress((void**)&Sh,  g_S_h);  cudaGetSymbolAddress((void**)&Sl,  g_S_l);
    cudaGetSymbolAddress((void**)&Kh,  g_K_h);  cudaGetSymbolAddress((void**)&Kl,  g_K_l);
    cudaGetSymbolAddress((void**)&VT,  g_VT);
    cudaGetSymbolAddress((void**)&Ath, g_At_h); cudaGetSymbolAddress((void**)&Atl, g_At_l);

    cudaFuncSetAttribute(mma_gemm<true, true>,
                         cudaFuncAttributeMaxDynamicSharedMemorySize, SMEM_3P);
    cudaFuncSetAttribute(mma_gemm<false, false>,
                         cudaFuncAttributeMaxDynamicSharedMemorySize, SMEM_3P);
    cudaFuncSetAttribute(mma_gemm_f16,
                         cudaFuncAttributeMaxDynamicSharedMemorySize, SMEM_2P);

    // Split inputs
    {
        size_t n;
        n = (size_t)cNS * cHID; split_kernel<<<(unsigned)(n / 1024), 256>>>(Xs, Xsh, Xsl, n);
        n = (size_t)cNK * cKED; split_kernel<<<(unsigned)(n / 1024), 256>>>(Xk, Xkh, Xkl, n);
        n = (size_t)cHID * cHID; split_kernel<<<(unsigned)(n / 1024), 256>>>(Ws, Wsh, Wsl, n);
        n = (size_t)cHID * cKED; split_kernel<<<(unsigned)(n / 1024), 256>>>(Wk, Wkh, Wkl, n);
    }
    // V^T fp16 plane
    transpose_half_kernel<<<dim3(cKED / 32, cNK / 32), dim3(32, 8)>>>(
        Xk, VT, cNK, cKED);

    // S = Xs @ Ws^T + bs  -> split planes  [8192, 1024]
    mma_gemm<true, true><<<dim3(cHID / 128, cNS / 128), 256, SMEM_3P>>>(
        Xsh, Xsl, Wsh, Wsl, bs, nullptr, Sh, Sl, cNS, cHID, cHID);

    // K = Xk @ Wk^T + bk  -> split planes  [8192, 1024]
    mma_gemm<true, true><<<dim3(cHID / 128, cNK / 128), 256, SMEM_3P>>>(
        Xkh, Xkl, Wkh, Wkl, bk, nullptr, Kh, Kl, cNK, cHID, cKED);

    // scores = S @ K^T -> fp32 into attns region  [8192, 8192]
    mma_gemm<false, false><<<dim3(cNK / 128, cNS / 128), 256, SMEM_3P>>>(
        Sh, Sl, Kh, Kl, nullptr, attns, nullptr, nullptr, cNS, cNK, cHID);

    // softmax over axis 0, in place; emit fp16 split planes
    softmax_pass1<<<dim3(cNK / 1024, CHUNKS), 256>>>(attns);
    softmax_pass2<<<cNK / 256, 256>>>();
    softmax_pass3<<<dim3(cNK / 1024, cNS), 256>>>(attns, Ath, Atl);

    // fused = attns @ V = (Ath+Atl) @ VT^T  [8192, 2048], 2-pass fp16
    mma_gemm_f16<<<dim3(cKED / 128, cNS / 128), 256, SMEM_2P>>>(
        Ath, Atl, VT, fused, cNS, cKED, cNK);
}

// round 6
// speedup vs baseline: 1.7263x; 1.3606x over previous
#include <cuda_runtime.h>
#include <cuda_bf16.h>
#include <cuda_fp16.h>
#include <stdint.h>

// ---------------------------------------------------------------------------
// Problem dims
// ---------------------------------------------------------------------------
static const int cNS  = 8192;
static const int cNK  = 8192;
static const int cHID = 1024;
static const int cKED = 2048;
static const int CHUNKS = 64;  // softmax row chunks (128 rows each)

// ---------------------------------------------------------------------------
// Scratch (__device__ globals; allocation-free)
// ---------------------------------------------------------------------------
__device__ __nv_bfloat16 g_Xs_h[(size_t)cNS * cHID];
__device__ __nv_bfloat16 g_Xs_l[(size_t)cNS * cHID];
__device__ __nv_bfloat16 g_Xk_h[(size_t)cNK * cKED];
__device__ __nv_bfloat16 g_Xk_l[(size_t)cNK * cKED];
__device__ __nv_bfloat16 g_Ws_h[(size_t)cHID * cHID];
__device__ __nv_bfloat16 g_Ws_l[(size_t)cHID * cHID];
__device__ __nv_bfloat16 g_Wk_h[(size_t)cHID * cKED];
__device__ __nv_bfloat16 g_Wk_l[(size_t)cHID * cKED];
__device__ __nv_bfloat16 g_S_h[(size_t)cNS * cHID];
__device__ __nv_bfloat16 g_S_l[(size_t)cNS * cHID];
__device__ __nv_bfloat16 g_K_h[(size_t)cNK * cHID];
__device__ __nv_bfloat16 g_K_l[(size_t)cNK * cHID];
__device__ __half g_VT[(size_t)cKED * cNK];            // V^T fp16 [2048, 8192]
__device__ __half g_At[(size_t)cNS * cNK];             // attns fp16 (single plane)
__device__ float g_pm[CHUNKS * cNK];
__device__ float g_ps[CHUNKS * cNK];
__device__ float g_m[cNK];
__device__ float g_rs[cNK];

// ---------------------------------------------------------------------------
// Helpers
// ---------------------------------------------------------------------------
__device__ __forceinline__ uint32_t smem_to_u32(const void* p) {
    uint32_t a;
    asm("{ .reg .u64 t; cvta.to.shared.u64 t, %1; cvt.u32.u64 %0, t; }"
        : "=r"(a) : "l"(p));
    return a;
}

__device__ __forceinline__ void cp_async16(uint32_t smem_addr, const void* gptr) {
    asm volatile("cp.async.cg.shared.global [%0], [%1], 16;\n"
                 :: "r"(smem_addr), "l"(__cvta_generic_to_global(gptr)));
}
__device__ __forceinline__ void cp_commit() {
    asm volatile("cp.async.commit_group;\n" ::: "memory");
}
template <int N>
__device__ __forceinline__ void cp_wait() {
    asm volatile("cp.async.wait_group %0;\n" :: "n"(N) : "memory");
}

__device__ __forceinline__ void ldsm_x4(uint32_t (&r)[4], uint32_t addr) {
    asm volatile("ldmatrix.sync.aligned.m8n8.x4.shared.b16 {%0,%1,%2,%3}, [%4];\n"
                 : "=r"(r[0]), "=r"(r[1]), "=r"(r[2]), "=r"(r[3]) : "r"(addr));
}

__device__ __forceinline__ void mma16816(float (&c)[4], const uint32_t (&a)[4],
                                         uint32_t b0, uint32_t b1) {
    asm volatile(
        "mma.sync.aligned.m16n8k16.row.col.f32.bf16.bf16.f32 "
        "{%0,%1,%2,%3}, {%4,%5,%6,%7}, {%8,%9}, {%0,%1,%2,%3};\n"
        : "+f"(c[0]), "+f"(c[1]), "+f"(c[2]), "+f"(c[3])
        : "r"(a[0]), "r"(a[1]), "r"(a[2]), "r"(a[3]), "r"(b0), "r"(b1));
}

__device__ __forceinline__ void mma16816h(float (&c)[4], const uint32_t (&a)[4],
                                          uint32_t b0, uint32_t b1) {
    asm volatile(
        "mma.sync.aligned.m16n8k16.row.col.f32.f16.f16.f32 "
        "{%0,%1,%2,%3}, {%4,%5,%6,%7}, {%8,%9}, {%0,%1,%2,%3};\n"
        : "+f"(c[0]), "+f"(c[1]), "+f"(c[2]), "+f"(c[3])
        : "r"(a[0]), "r"(a[1]), "r"(a[2]), "r"(a[3]), "r"(b0), "r"(b1));
}

__device__ __forceinline__ void split1(float x, __nv_bfloat16& h, __nv_bfloat16& l) {
    h = __float2bfloat16(x);
    l = __float2bfloat16(x - __bfloat162float(h));
}

// ---------------------------------------------------------------------------
// Split / transpose preprocessing
// ---------------------------------------------------------------------------
__global__ void split_kernel(const float* __restrict__ in,
                             __nv_bfloat16* __restrict__ hi,
                             __nv_bfloat16* __restrict__ lo, size_t n) {
    size_t i = ((size_t)blockIdx.x * 256 + threadIdx.x) * 4;
    if (i >= n) return;
    float4 v = *(const float4*)(in + i);
    __nv_bfloat16 h0, h1, h2, h3, l0, l1, l2, l3;
    split1(v.x, h0, l0); split1(v.y, h1, l1);
    split1(v.z, h2, l2); split1(v.w, h3, l3);
    *(__nv_bfloat162*)(hi + i)     = __nv_bfloat162(h0, h1);
    *(__nv_bfloat162*)(hi + i + 2) = __nv_bfloat162(h2, h3);
    *(__nv_bfloat162*)(lo + i)     = __nv_bfloat162(l0, l1);
    *(__nv_bfloat162*)(lo + i + 2) = __nv_bfloat162(l2, l3);
}

// Transpose fp32 [R, C] -> fp16 [C, R]
__global__ void transpose_half_kernel(const float* __restrict__ in,
                                      __half* __restrict__ out,
                                      int R, int C) {
    __shared__ float t[32][33];
    int c0 = blockIdx.x * 32, r0 = blockIdx.y * 32;
    int tx = threadIdx.x, ty = threadIdx.y;
#pragma unroll
    for (int j = 0; j < 4; ++j)
        t[ty + j * 8][tx] = in[(size_t)(r0 + ty + j * 8) * C + c0 + tx];
    __syncthreads();
#pragma unroll
    for (int j = 0; j < 4; ++j) {
        float v = t[tx][ty + j * 8];
        out[(size_t)(c0 + ty + j * 8) * R + r0 + tx] = __float2half(v);
    }
}

// ---------------------------------------------------------------------------
// Common GEMM geometry: 128x128 CTA tile, BK=32, 3-stage cp.async pipeline,
// 8 warps (2x4), warp tile 64x32, 80B-padded SMEM rows (conflict-free ldsm).
// ---------------------------------------------------------------------------
static const int ROWB    = 80;                 // 64B data + 16B pad
static const int TILE_B  = 128 * ROWB;         // 10240 B per plane-tile

// === 3-pass split-bf16 GEMM: C = (Ah+Al) * (Bh+Bl)^T (+bias) ===
static const int STAGE_B3 = 4 * TILE_B;        // Ah, Al, Bh, Bl
static const int SMEM_3P  = 3 * STAGE_B3;      // 122880

template <bool BIAS, bool SPLIT>
__global__ __launch_bounds__(256, 1)
void mma_gemm(const __nv_bfloat16* __restrict__ Ah, const __nv_bfloat16* __restrict__ Al,
              const __nv_bfloat16* __restrict__ Bh, const __nv_bfloat16* __restrict__ Bl,
              const float* __restrict__ bias,
              float* __restrict__ C,
              __nv_bfloat16* __restrict__ Ch, __nv_bfloat16* __restrict__ Cl,
              int M, int N, int K)
{
    extern __shared__ char sm[];
    const uint32_t sbase = smem_to_u32(sm);

    const int tid = threadIdx.x;
    const int wid = tid >> 5, lane = tid & 31;
    const int wm = wid >> 2, wn = wid & 3;      // 2 x 4 warp grid
    const int row0 = blockIdx.y * 128, col0 = blockIdx.x * 128;

    const __nv_bfloat16* srcs[4] = {
        Ah + (size_t)row0 * K, Al + (size_t)row0 * K,
        Bh + (size_t)col0 * K, Bl + (size_t)col0 * K };

    const int NT = K >> 5;

    auto issue_loads = [&](int kt, int s) {
        const int k0 = kt << 5;
#pragma unroll
        for (int i = 0; i < 8; ++i) {
            int q = tid + i * 256;
            int t = q >> 9, idx = q & 511;
            int row = idx >> 2, c = idx & 3;
            const __nv_bfloat16* g = srcs[t] + (size_t)row * K + k0 + c * 8;
            uint32_t d = sbase + s * STAGE_B3 + t * TILE_B + row * ROWB + c * 16;
            cp_async16(d, g);
        }
    };

    issue_loads(0, 0); cp_commit();
    issue_loads(1, 1); cp_commit();

    float acc[4][4][4];
#pragma unroll
    for (int i = 0; i < 4; ++i)
#pragma unroll
        for (int j = 0; j < 4; ++j)
#pragma unroll
            for (int v = 0; v < 4; ++v) acc[i][j][v] = 0.f;

    const int lrow = lane & 15, lcol = lane >> 4;

    for (int kt = 0; kt < NT; ++kt) {
        const int s = kt % 3;
        cp_wait<1>();
        __syncthreads();
        if (kt + 2 < NT) issue_loads(kt + 2, (kt + 2) % 3);
        cp_commit();

#pragma unroll
        for (int ks = 0; ks < 2; ++ks) {
            uint32_t ah[4][4], al[4][4], bh[2][4], bl[2][4];
            const uint32_t abase = sbase + s * STAGE_B3
                + (wm * 64 + lrow) * ROWB + ks * 32 + lcol * 16;
#pragma unroll
            for (int mi = 0; mi < 4; ++mi) {
                ldsm_x4(ah[mi], abase + mi * 16 * ROWB);
                ldsm_x4(al[mi], abase + mi * 16 * ROWB + TILE_B);
            }
            const uint32_t bbase = sbase + s * STAGE_B3 + 2 * TILE_B
                + (wn * 32 + lrow) * ROWB + ks * 32 + lcol * 16;
#pragma unroll
            for (int bj = 0; bj < 2; ++bj) {
                ldsm_x4(bh[bj], bbase + bj * 16 * ROWB);
                ldsm_x4(bl[bj], bbase + bj * 16 * ROWB + TILE_B);
            }
#pragma unroll
            for (int mi = 0; mi < 4; ++mi) {
#pragma unroll
                for (int jn = 0; jn < 4; ++jn) {
                    const int bj = jn >> 1, hf = jn & 1;
                    mma16816(acc[mi][jn], ah[mi], bh[bj][hf], bh[bj][hf + 2]);
                    mma16816(acc[mi][jn], ah[mi], bl[bj][hf], bl[bj][hf + 2]);
                    mma16816(acc[mi][jn], al[mi], bh[bj][hf], bh[bj][hf + 2]);
                }
            }
        }
    }

    const int g = lane >> 2, cq = (lane & 3) * 2;
#pragma unroll
    for (int mi = 0; mi < 4; ++mi) {
#pragma unroll
        for (int jn = 0; jn < 4; ++jn) {
            const int r0w = row0 + wm * 64 + mi * 16 + g;
            const int cc = col0 + wn * 32 + jn * 8 + cq;
            float v0 = acc[mi][jn][0], v1 = acc[mi][jn][1];
            float v2 = acc[mi][jn][2], v3 = acc[mi][jn][3];
            if (BIAS) {
                float b0 = bias[cc], b1 = bias[cc + 1];
                v0 += b0; v1 += b1; v2 += b0; v3 += b1;
            }
            if (SPLIT) {
                __nv_bfloat16 h0, h1, h2, h3, l0, l1, l2, l3;
                split1(v0, h0, l0); split1(v1, h1, l1);
                split1(v2, h2, l2); split1(v3, h3, l3);
                size_t o0 = (size_t)r0w * N + cc;
                size_t o1 = (size_t)(r0w + 8) * N + cc;
                *(__nv_bfloat162*)(Ch + o0) = __nv_bfloat162(h0, h1);
                *(__nv_bfloat162*)(Cl + o0) = __nv_bfloat162(l0, l1);
                *(__nv_bfloat162*)(Ch + o1) = __nv_bfloat162(h2, h3);
                *(__nv_bfloat162*)(Cl + o1) = __nv_bfloat162(l2, l3);
            } else {
                *(float2*)(C + (size_t)r0w * N + cc)       = make_float2(v0, v1);
                *(float2*)(C + (size_t)(r0w + 8) * N + cc) = make_float2(v2, v3);
            }
        }
    }
}

// === 1-pass fp16 GEMM: C = A * B^T, fp32 accumulate ===
static const int STAGE_B1 = 2 * TILE_B;        // A, B
static const int SMEM_1P  = 3 * STAGE_B1;      // 61440

__global__ __launch_bounds__(256, 1)
void mma_gemm_f16(const __half* __restrict__ A, const __half* __restrict__ B,
                  float* __restrict__ C, int M, int N, int K)
{
    extern __shared__ char sm[];
    const uint32_t sbase = smem_to_u32(sm);

    const int tid = threadIdx.x;
    const int wid = tid >> 5, lane = tid & 31;
    const int wm = wid >> 2, wn = wid & 3;
    const int row0 = blockIdx.y * 128, col0 = blockIdx.x * 128;

    const __half* srcs[2] = { A + (size_t)row0 * K, B + (size_t)col0 * K };

    const int NT = K >> 5;

    auto issue_loads = [&](int kt, int s) {
        const int k0 = kt << 5;
#pragma unroll
        for (int i = 0; i < 4; ++i) {
            int q = tid + i * 256;
            int t = q >> 9, idx = q & 511;
            int row = idx >> 2, c = idx & 3;
            const __half* g = srcs[t] + (size_t)row * K + k0 + c * 8;
            uint32_t d = sbase + s * STAGE_B1 + t * TILE_B + row * ROWB + c * 16;
            cp_async16(d, g);
        }
    };

    issue_loads(0, 0); cp_commit();
    issue_loads(1, 1); cp_commit();

    float acc[4][4][4];
#pragma unroll
    for (int i = 0; i < 4; ++i)
#pragma unroll
        for (int j = 0; j < 4; ++j)
#pragma unroll
            for (int v = 0; v < 4; ++v) acc[i][j][v] = 0.f;

    const int lrow = lane & 15, lcol = lane >> 4;

    for (int kt = 0; kt < NT; ++kt) {
        const int s = kt % 3;
        cp_wait<1>();
        __syncthreads();
        if (kt + 2 < NT) issue_loads(kt + 2, (kt + 2) % 3);
        cp_commit();

#pragma unroll
        for (int ks = 0; ks < 2; ++ks) {
            uint32_t aa[4][4], bb[2][4];
            const uint32_t abase = sbase + s * STAGE_B1
                + (wm * 64 + lrow) * ROWB + ks * 32 + lcol * 16;
#pragma unroll
            for (int mi = 0; mi < 4; ++mi)
                ldsm_x4(aa[mi], abase + mi * 16 * ROWB);
            const uint32_t bbase = sbase + s * STAGE_B1 + TILE_B
                + (wn * 32 + lrow) * ROWB + ks * 32 + lcol * 16;
#pragma unroll
            for (int bj = 0; bj < 2; ++bj)
                ldsm_x4(bb[bj], bbase + bj * 16 * ROWB);
#pragma unroll
            for (int mi = 0; mi < 4; ++mi) {
#pragma unroll
                for (int jn = 0; jn < 4; ++jn) {
                    const int bj = jn >> 1, hf = jn & 1;
                    mma16816h(acc[mi][jn], aa[mi], bb[bj][hf], bb[bj][hf + 2]);
                }
            }
        }
    }

    const int g = lane >> 2, cq = (lane & 3) * 2;
#pragma unroll
    for (int mi = 0; mi < 4; ++mi) {
#pragma unroll
        for (int jn = 0; jn < 4; ++jn) {
            const int r0w = row0 + wm * 64 + mi * 16 + g;
            const int cc = col0 + wn * 32 + jn * 8 + cq;
            *(float2*)(C + (size_t)r0w * N + cc)
                = make_float2(acc[mi][jn][0], acc[mi][jn][1]);
            *(float2*)(C + (size_t)(r0w + 8) * N + cc)
                = make_float2(acc[mi][jn][2], acc[mi][jn][3]);
        }
    }
}

// ---------------------------------------------------------------------------
// Column softmax (axis 0) on scores [Ns, Nk]
// ---------------------------------------------------------------------------
__global__ void softmax_pass1(const float* __restrict__ sc) {
    const int j4 = (blockIdx.x * 256 + threadIdx.x) * 4;
    const int chunk = blockIdx.y;
    const int rows = cNS / CHUNKS;
    const size_t i0 = (size_t)chunk * rows;
    float m0 = -1e30f, m1 = -1e30f, m2 = -1e30f, m3 = -1e30f;
    float s0 = 0.f, s1 = 0.f, s2 = 0.f, s3 = 0.f;
#pragma unroll 4
    for (int i = 0; i < rows; ++i) {
        float4 x = *(const float4*)(sc + (i0 + i) * cNK + j4);
        float n0 = fmaxf(m0, x.x); s0 = s0 * __expf(m0 - n0) + __expf(x.x - n0); m0 = n0;
        float n1 = fmaxf(m1, x.y); s1 = s1 * __expf(m1 - n1) + __expf(x.y - n1); m1 = n1;
        float n2 = fmaxf(m2, x.z); s2 = s2 * __expf(m2 - n2) + __expf(x.z - n2); m2 = n2;
        float n3 = fmaxf(m3, x.w); s3 = s3 * __expf(m3 - n3) + __expf(x.w - n3); m3 = n3;
    }
    g_pm[(size_t)chunk * cNK + j4 + 0] = m0; g_ps[(size_t)chunk * cNK + j4 + 0] = s0;
    g_pm[(size_t)chunk * cNK + j4 + 1] = m1; g_ps[(size_t)chunk * cNK + j4 + 1] = s1;
    g_pm[(size_t)chunk * cNK + j4 + 2] = m2; g_ps[(size_t)chunk * cNK + j4 + 2] = s2;
    g_pm[(size_t)chunk * cNK + j4 + 3] = m3; g_ps[(size_t)chunk * cNK + j4 + 3] = s3;
}

__global__ void softmax_pass2() {
    const int j = blockIdx.x * 256 + threadIdx.x;
    float m = -1e30f, s = 0.f;
#pragma unroll 8
    for (int c = 0; c < CHUNKS; ++c) {
        float pm = g_pm[(size_t)c * cNK + j];
        float ps = g_ps[(size_t)c * cNK + j];
        float nm = fmaxf(m, pm);
        s = s * __expf(m - nm) + ps * __expf(pm - nm);
        m = nm;
    }
    g_m[j] = m;
    g_rs[j] = 1.f / s;
}

// Normalize in place + emit single fp16 plane for the fused GEMM.
__global__ void softmax_pass3(float* __restrict__ sc, __half* __restrict__ at) {
    const int j4 = (blockIdx.x * 256 + threadIdx.x) * 4;
    const size_t i = blockIdx.y;
    float4 x = *(float4*)(sc + i * cNK + j4);
    float4 m = *(const float4*)(&g_m[j4]);
    float4 rs = *(const float4*)(&g_rs[j4]);
    x.x = __expf(x.x - m.x) * rs.x;
    x.y = __expf(x.y - m.y) * rs.y;
    x.z = __expf(x.z - m.z) * rs.z;
    x.w = __expf(x.w - m.w) * rs.w;
    *(float4*)(sc + i * cNK + j4) = x;
    __half2 p0 = __floats2half2_rn(x.x, x.y);
    __half2 p1 = __floats2half2_rn(x.z, x.w);
    size_t off = i * cNK + j4;
    *(__half2*)(at + off)     = p0;
    *(__half2*)(at + off + 2) = p1;
}

// ---------------------------------------------------------------------------
// Launch
// ---------------------------------------------------------------------------
extern "C" void kernel_launch(void* const* d_in, const int* in_sizes, int n_in,
                              void* d_out, int out_size)
{
    const float* Xs = (const float*)d_in[0];
    const float* Xk = (const float*)d_in[1];
    const float* Ws = (const float*)d_in[2];
    const float* bs = (const float*)d_in[3];
    const float* Wk = (const float*)d_in[4];
    const float* bk = (const float*)d_in[5];

    float* attns = (float*)d_out;
    float* fused = attns + (size_t)cNS * cNK;

    __nv_bfloat16 *Xsh, *Xsl, *Xkh, *Xkl, *Wsh, *Wsl, *Wkh, *Wkl;
    __nv_bfloat16 *Sh, *Sl, *Kh, *Kl;
    __half *VT, *At;
    cudaGetSymbolAddress((void**)&Xsh, g_Xs_h); cudaGetSymbolAddress((void**)&Xsl, g_Xs_l);
    cudaGetSymbolAddress((void**)&Xkh, g_Xk_h); cudaGetSymbolAddress((void**)&Xkl, g_Xk_l);
    cudaGetSymbolAddress((void**)&Wsh, g_Ws_h); cudaGetSymbolAddress((void**)&Wsl, g_Ws_l);
    cudaGetSymbolAddress((void**)&Wkh, g_Wk_h); cudaGetSymbolAddress((void**)&Wkl, g_Wk_l);
    cudaGetSymbolAddress((void**)&Sh,  g_S_h);  cudaGetSymbolAddress((void**)&Sl,  g_S_l);
    cudaGetSymbolAddress((void**)&Kh,  g_K_h);  cudaGetSymbolAddress((void**)&Kl,  g_K_l);
    cudaGetSymbolAddress((void**)&VT,  g_VT);
    cudaGetSymbolAddress((void**)&At,  g_At);

    cudaFuncSetAttribute(mma_gemm<true, true>,
                         cudaFuncAttributeMaxDynamicSharedMemorySize, SMEM_3P);
    cudaFuncSetAttribute(mma_gemm<false, false>,
                         cudaFuncAttributeMaxDynamicSharedMemorySize, SMEM_3P);
    cudaFuncSetAttribute(mma_gemm_f16,
                         cudaFuncAttributeMaxDynamicSharedMemorySize, SMEM_1P);

    // Split inputs
    {
        size_t n;
        n = (size_t)cNS * cHID; split_kernel<<<(unsigned)(n / 1024), 256>>>(Xs, Xsh, Xsl, n);
        n = (size_t)cNK * cKED; split_kernel<<<(unsigned)(n / 1024), 256>>>(Xk, Xkh, Xkl, n);
        n = (size_t)cHID * cHID; split_kernel<<<(unsigned)(n / 1024), 256>>>(Ws, Wsh, Wsl, n);
        n = (size_t)cHID * cKED; split_kernel<<<(unsigned)(n / 1024), 256>>>(Wk, Wkh, Wkl, n);
    }
    // V^T fp16 plane
    transpose_half_kernel<<<dim3(cKED / 32, cNK / 32), dim3(32, 8)>>>(
        Xk, VT, cNK, cKED);

    // S = Xs @ Ws^T + bs  -> split planes  [8192, 1024]
    mma_gemm<true, true><<<dim3(cHID / 128, cNS / 128), 256, SMEM_3P>>>(
        Xsh, Xsl, Wsh, Wsl, bs, nullptr, Sh, Sl, cNS, cHID, cHID);

    // K = Xk @ Wk^T + bk  -> split planes  [8192, 1024]
    mma_gemm<true, true><<<dim3(cHID / 128, cNK / 128), 256, SMEM_3P>>>(
        Xkh, Xkl, Wkh, Wkl, bk, nullptr, Kh, Kl, cNK, cHID, cKED);

    // scores = S @ K^T -> fp32 into attns region  [8192, 8192]
    mma_gemm<false, false><<<dim3(cNK / 128, cNS / 128), 256, SMEM_3P>>>(
        Sh, Sl, Kh, Kl, nullptr, attns, nullptr, nullptr, cNS, cNK, cHID);

    // softmax over axis 0, in place; emit fp16 plane
    softmax_pass1<<<dim3(cNK / 1024, CHUNKS), 256>>>(attns);
    softmax_pass2<<<cNK / 256, 256>>>();
    softmax_pass3<<<dim3(cNK / 1024, cNS), 256>>>(attns, At);

    // fused = attns @ V = At @ VT^T  [8192, 2048], 1-pass fp16
    mma_gemm_f16<<<dim3(cKED / 128, cNS / 128), 256, SMEM_1P>>>(
        At, VT, fused, cNS, cKED, cNK);
}

// round 7
// speedup vs baseline: 1.7859x; 1.0346x over previous
#include <cuda_runtime.h>
#include <cuda_bf16.h>
#include <cuda_fp16.h>
#include <stdint.h>

// ---------------------------------------------------------------------------
// Problem dims
// ---------------------------------------------------------------------------
static const int cNS  = 8192;
static const int cNK  = 8192;
static const int cHID = 1024;
static const int cKED = 2048;
static const int CHUNKS = 64;  // softmax row chunks = one 128-row CTA tile each

// ---------------------------------------------------------------------------
// Scratch (__device__ globals; allocation-free)
// ---------------------------------------------------------------------------
__device__ __nv_bfloat16 g_Xs_h[(size_t)cNS * cHID];
__device__ __nv_bfloat16 g_Xs_l[(size_t)cNS * cHID];
__device__ __nv_bfloat16 g_Xk_h[(size_t)cNK * cKED];
__device__ __nv_bfloat16 g_Xk_l[(size_t)cNK * cKED];
__device__ __nv_bfloat16 g_Ws_h[(size_t)cHID * cHID];
__device__ __nv_bfloat16 g_Ws_l[(size_t)cHID * cHID];
__device__ __nv_bfloat16 g_Wk_h[(size_t)cHID * cKED];
__device__ __nv_bfloat16 g_Wk_l[(size_t)cHID * cKED];
__device__ __nv_bfloat16 g_S_h[(size_t)cNS * cHID];
__device__ __nv_bfloat16 g_S_l[(size_t)cNS * cHID];
__device__ __nv_bfloat16 g_K_h[(size_t)cNK * cHID];
__device__ __nv_bfloat16 g_K_l[(size_t)cNK * cHID];
__device__ __half g_VT[(size_t)cKED * cNK];            // V^T fp16 [2048, 8192]
__device__ __half g_At[(size_t)cNS * cNK];             // attns fp16 (single plane)
__device__ float g_pm[(size_t)CHUNKS * cNK];
__device__ float g_ps[(size_t)CHUNKS * cNK];
__device__ float g_m[cNK];
__device__ float g_rs[cNK];

// ---------------------------------------------------------------------------
// Helpers
// ---------------------------------------------------------------------------
__device__ __forceinline__ uint32_t smem_to_u32(const void* p) {
    uint32_t a;
    asm("{ .reg .u64 t; cvta.to.shared.u64 t, %1; cvt.u32.u64 %0, t; }"
        : "=r"(a) : "l"(p));
    return a;
}

__device__ __forceinline__ void cp_async16(uint32_t smem_addr, const void* gptr) {
    asm volatile("cp.async.cg.shared.global [%0], [%1], 16;\n"
                 :: "r"(smem_addr), "l"(__cvta_generic_to_global(gptr)));
}
__device__ __forceinline__ void cp_commit() {
    asm volatile("cp.async.commit_group;\n" ::: "memory");
}
template <int N>
__device__ __forceinline__ void cp_wait() {
    asm volatile("cp.async.wait_group %0;\n" :: "n"(N) : "memory");
}

__device__ __forceinline__ void ldsm_x4(uint32_t (&r)[4], uint32_t addr) {
    asm volatile("ldmatrix.sync.aligned.m8n8.x4.shared.b16 {%0,%1,%2,%3}, [%4];\n"
                 : "=r"(r[0]), "=r"(r[1]), "=r"(r[2]), "=r"(r[3]) : "r"(addr));
}

__device__ __forceinline__ void mma16816(float (&c)[4], const uint32_t (&a)[4],
                                         uint32_t b0, uint32_t b1) {
    asm volatile(
        "mma.sync.aligned.m16n8k16.row.col.f32.bf16.bf16.f32 "
        "{%0,%1,%2,%3}, {%4,%5,%6,%7}, {%8,%9}, {%0,%1,%2,%3};\n"
        : "+f"(c[0]), "+f"(c[1]), "+f"(c[2]), "+f"(c[3])
        : "r"(a[0]), "r"(a[1]), "r"(a[2]), "r"(a[3]), "r"(b0), "r"(b1));
}

__device__ __forceinline__ void mma16816h(float (&c)[4], const uint32_t (&a)[4],
                                          uint32_t b0, uint32_t b1) {
    asm volatile(
        "mma.sync.aligned.m16n8k16.row.col.f32.f16.f16.f32 "
        "{%0,%1,%2,%3}, {%4,%5,%6,%7}, {%8,%9}, {%0,%1,%2,%3};\n"
        : "+f"(c[0]), "+f"(c[1]), "+f"(c[2]), "+f"(c[3])
        : "r"(a[0]), "r"(a[1]), "r"(a[2]), "r"(a[3]), "r"(b0), "r"(b1));
}

__device__ __forceinline__ void split1(float x, __nv_bfloat16& h, __nv_bfloat16& l) {
    h = __float2bfloat16(x);
    l = __float2bfloat16(x - __bfloat162float(h));
}

// ---------------------------------------------------------------------------
// Split / fused split+transpose preprocessing
// ---------------------------------------------------------------------------
__global__ void split_kernel(const float* __restrict__ in,
                             __nv_bfloat16* __restrict__ hi,
                             __nv_bfloat16* __restrict__ lo, size_t n) {
    size_t i = ((size_t)blockIdx.x * 256 + threadIdx.x) * 4;
    if (i >= n) return;
    float4 v = *(const float4*)(in + i);
    __nv_bfloat16 h0, h1, h2, h3, l0, l1, l2, l3;
    split1(v.x, h0, l0); split1(v.y, h1, l1);
    split1(v.z, h2, l2); split1(v.w, h3, l3);
    *(__nv_bfloat162*)(hi + i)     = __nv_bfloat162(h0, h1);
    *(__nv_bfloat162*)(hi + i + 2) = __nv_bfloat162(h2, h3);
    *(__nv_bfloat162*)(lo + i)     = __nv_bfloat162(l0, l1);
    *(__nv_bfloat162*)(lo + i + 2) = __nv_bfloat162(l2, l3);
}

// Read Xk once: emit bf16 hi/lo planes (row-major) + fp16 V^T (transposed).
__global__ void split_transpose_kernel(const float* __restrict__ in,
                                       __nv_bfloat16* __restrict__ hi,
                                       __nv_bfloat16* __restrict__ lo,
                                       __half* __restrict__ vt,
                                       int R, int C) {
    __shared__ float t[32][33];
    int c0 = blockIdx.x * 32, r0 = blockIdx.y * 32;
    int tx = threadIdx.x, ty = threadIdx.y;
#pragma unroll
    for (int j = 0; j < 4; ++j) {
        float v = in[(size_t)(r0 + ty + j * 8) * C + c0 + tx];
        t[ty + j * 8][tx] = v;
        __nv_bfloat16 h, l; split1(v, h, l);
        size_t off = (size_t)(r0 + ty + j * 8) * C + c0 + tx;
        hi[off] = h; lo[off] = l;
    }
    __syncthreads();
#pragma unroll
    for (int j = 0; j < 4; ++j)
        vt[(size_t)(c0 + ty + j * 8) * R + r0 + tx] = __float2half(t[tx][ty + j * 8]);
}

// ---------------------------------------------------------------------------
// Common GEMM geometry: 128x128 CTA tile, BK=32, 3-stage cp.async pipeline,
// 8 warps (2x4), warp tile 64x32, 80B-padded SMEM rows (conflict-free ldsm).
// ---------------------------------------------------------------------------
static const int ROWB    = 80;                 // 64B data + 16B pad
static const int TILE_B  = 128 * ROWB;         // 10240 B per plane-tile

// === 3-pass split-bf16 GEMM: C = (Ah+Al) * (Bh+Bl)^T (+bias) ===
// STATS: also emit per-column chunk max/sumexp (softmax pass-1) from registers.
static const int STAGE_B3 = 4 * TILE_B;        // Ah, Al, Bh, Bl
static const int SMEM_3P  = 3 * STAGE_B3;      // 122880

template <bool BIAS, bool SPLIT, bool STATS>
__global__ __launch_bounds__(256, 1)
void mma_gemm(const __nv_bfloat16* __restrict__ Ah, const __nv_bfloat16* __restrict__ Al,
              const __nv_bfloat16* __restrict__ Bh, const __nv_bfloat16* __restrict__ Bl,
              const float* __restrict__ bias,
              float* __restrict__ C,
              __nv_bfloat16* __restrict__ Ch, __nv_bfloat16* __restrict__ Cl,
              int M, int N, int K)
{
    extern __shared__ char sm[];
    const uint32_t sbase = smem_to_u32(sm);

    const int tid = threadIdx.x;
    const int wid = tid >> 5, lane = tid & 31;
    const int wm = wid >> 2, wn = wid & 3;      // 2 x 4 warp grid
    const int row0 = blockIdx.y * 128, col0 = blockIdx.x * 128;

    const __nv_bfloat16* srcs[4] = {
        Ah + (size_t)row0 * K, Al + (size_t)row0 * K,
        Bh + (size_t)col0 * K, Bl + (size_t)col0 * K };

    const int NT = K >> 5;

    auto issue_loads = [&](int kt, int s) {
        const int k0 = kt << 5;
#pragma unroll
        for (int i = 0; i < 8; ++i) {
            int q = tid + i * 256;
            int t = q >> 9, idx = q & 511;
            int row = idx >> 2, c = idx & 3;
            const __nv_bfloat16* g = srcs[t] + (size_t)row * K + k0 + c * 8;
            uint32_t d = sbase + s * STAGE_B3 + t * TILE_B + row * ROWB + c * 16;
            cp_async16(d, g);
        }
    };

    issue_loads(0, 0); cp_commit();
    issue_loads(1, 1); cp_commit();

    float acc[4][4][4];
#pragma unroll
    for (int i = 0; i < 4; ++i)
#pragma unroll
        for (int j = 0; j < 4; ++j)
#pragma unroll
            for (int v = 0; v < 4; ++v) acc[i][j][v] = 0.f;

    const int lrow = lane & 15, lcol = lane >> 4;

    for (int kt = 0; kt < NT; ++kt) {
        const int s = kt % 3;
        cp_wait<1>();
        __syncthreads();
        if (kt + 2 < NT) issue_loads(kt + 2, (kt + 2) % 3);
        cp_commit();

#pragma unroll
        for (int ks = 0; ks < 2; ++ks) {
            uint32_t ah[4][4], al[4][4], bh[2][4], bl[2][4];
            const uint32_t abase = sbase + s * STAGE_B3
                + (wm * 64 + lrow) * ROWB + ks * 32 + lcol * 16;
#pragma unroll
            for (int mi = 0; mi < 4; ++mi) {
                ldsm_x4(ah[mi], abase + mi * 16 * ROWB);
                ldsm_x4(al[mi], abase + mi * 16 * ROWB + TILE_B);
            }
            const uint32_t bbase = sbase + s * STAGE_B3 + 2 * TILE_B
                + (wn * 32 + lrow) * ROWB + ks * 32 + lcol * 16;
#pragma unroll
            for (int bj = 0; bj < 2; ++bj) {
                ldsm_x4(bh[bj], bbase + bj * 16 * ROWB);
                ldsm_x4(bl[bj], bbase + bj * 16 * ROWB + TILE_B);
            }
#pragma unroll
            for (int mi = 0; mi < 4; ++mi) {
#pragma unroll
                for (int jn = 0; jn < 4; ++jn) {
                    const int bj = jn >> 1, hf = jn & 1;
                    mma16816(acc[mi][jn], ah[mi], bh[bj][hf], bh[bj][hf + 2]);
                    mma16816(acc[mi][jn], ah[mi], bl[bj][hf], bl[bj][hf + 2]);
                    mma16816(acc[mi][jn], al[mi], bh[bj][hf], bh[bj][hf + 2]);
                }
            }
        }
    }

    const int g = lane >> 2, cq = (lane & 3) * 2;
#pragma unroll
    for (int mi = 0; mi < 4; ++mi) {
#pragma unroll
        for (int jn = 0; jn < 4; ++jn) {
            const int r0w = row0 + wm * 64 + mi * 16 + g;
            const int cc = col0 + wn * 32 + jn * 8 + cq;
            float v0 = acc[mi][jn][0], v1 = acc[mi][jn][1];
            float v2 = acc[mi][jn][2], v3 = acc[mi][jn][3];
            if (BIAS) {
                float b0 = bias[cc], b1 = bias[cc + 1];
                v0 += b0; v1 += b1; v2 += b0; v3 += b1;
            }
            if (SPLIT) {
                __nv_bfloat16 h0, h1, h2, h3, l0, l1, l2, l3;
                split1(v0, h0, l0); split1(v1, h1, l1);
                split1(v2, h2, l2); split1(v3, h3, l3);
                size_t o0 = (size_t)r0w * N + cc;
                size_t o1 = (size_t)(r0w + 8) * N + cc;
                *(__nv_bfloat162*)(Ch + o0) = __nv_bfloat162(h0, h1);
                *(__nv_bfloat162*)(Cl + o0) = __nv_bfloat162(l0, l1);
                *(__nv_bfloat162*)(Ch + o1) = __nv_bfloat162(h2, h3);
                *(__nv_bfloat162*)(Cl + o1) = __nv_bfloat162(l2, l3);
            } else {
                *(float2*)(C + (size_t)r0w * N + cc)       = make_float2(v0, v1);
                *(float2*)(C + (size_t)(r0w + 8) * N + cc) = make_float2(v2, v3);
            }
        }
    }

    if (STATS) {
        // Softmax pass-1 from registers: per-column max / sumexp over this
        // CTA's 128 rows (chunk == blockIdx.y). Drain cp.async tail before
        // reusing stage smem (outstanding loads may target stage 0).
        cp_wait<0>();
        __syncthreads();
        float* SM_M = (float*)sm;            // [2][128]
        float* SM_S = (float*)(sm + 1024);   // [2][128]
#pragma unroll
        for (int jn = 0; jn < 4; ++jn) {
            float m0 = -1e30f, m1 = -1e30f;
#pragma unroll
            for (int mi = 0; mi < 4; ++mi) {
                m0 = fmaxf(m0, fmaxf(acc[mi][jn][0], acc[mi][jn][2]));
                m1 = fmaxf(m1, fmaxf(acc[mi][jn][1], acc[mi][jn][3]));
            }
            float s0 = 0.f, s1 = 0.f;
#pragma unroll
            for (int mi = 0; mi < 4; ++mi) {
                s0 += __expf(acc[mi][jn][0] - m0) + __expf(acc[mi][jn][2] - m0);
                s1 += __expf(acc[mi][jn][1] - m1) + __expf(acc[mi][jn][3] - m1);
            }
            // reduce across the 8 lanes (stride 4) sharing these two columns
#pragma unroll
            for (int o = 4; o < 32; o <<= 1) {
                float mo = __shfl_xor_sync(0xffffffffu, m0, o);
                float so = __shfl_xor_sync(0xffffffffu, s0, o);
                float nm = fmaxf(m0, mo);
                s0 = s0 * __expf(m0 - nm) + so * __expf(mo - nm); m0 = nm;
                mo = __shfl_xor_sync(0xffffffffu, m1, o);
                so = __shfl_xor_sync(0xffffffffu, s1, o);
                nm = fmaxf(m1, mo);
                s1 = s1 * __expf(m1 - nm) + so * __expf(mo - nm); m1 = nm;
            }
            if ((lane >> 2) == 0) {
                int cit = wn * 32 + jn * 8 + (lane & 3) * 2;
                SM_M[wm * 128 + cit]     = m0;  SM_S[wm * 128 + cit]     = s0;
                SM_M[wm * 128 + cit + 1] = m1;  SM_S[wm * 128 + cit + 1] = s1;
            }
        }
        __syncthreads();
        if (tid < 128) {
            float ma = SM_M[tid], mb = SM_M[128 + tid];
            float sa = SM_S[tid], sb = SM_S[128 + tid];
            float nm = fmaxf(ma, mb);
            float s = sa * __expf(ma - nm) + sb * __expf(mb - nm);
            g_pm[(size_t)blockIdx.y * cNK + col0 + tid] = nm;
            g_ps[(size_t)blockIdx.y * cNK + col0 + tid] = s;
        }
    }
}

// === 1-pass fp16 GEMM: C = A * B^T, fp32 accumulate ===
static const int STAGE_B1 = 2 * TILE_B;        // A, B
static const int SMEM_1P  = 3 * STAGE_B1;      // 61440

__global__ __launch_bounds__(256, 1)
void mma_gemm_f16(const __half* __restrict__ A, const __half* __restrict__ B,
                  float* __restrict__ C, int M, int N, int K)
{
    extern __shared__ char sm[];
    const uint32_t sbase = smem_to_u32(sm);

    const int tid = threadIdx.x;
    const int wid = tid >> 5, lane = tid & 31;
    const int wm = wid >> 2, wn = wid & 3;
    const int row0 = blockIdx.y * 128, col0 = blockIdx.x * 128;

    const __half* srcs[2] = { A + (size_t)row0 * K, B + (size_t)col0 * K };

    const int NT = K >> 5;

    auto issue_loads = [&](int kt, int s) {
        const int k0 = kt << 5;
#pragma unroll
        for (int i = 0; i < 4; ++i) {
            int q = tid + i * 256;
            int t = q >> 9, idx = q & 511;
            int row = idx >> 2, c = idx & 3;
            const __half* g = srcs[t] + (size_t)row * K + k0 + c * 8;
            uint32_t d = sbase + s * STAGE_B1 + t * TILE_B + row * ROWB + c * 16;
            cp_async16(d, g);
        }
    };

    issue_loads(0, 0); cp_commit();
    issue_loads(1, 1); cp_commit();

    float acc[4][4][4];
#pragma unroll
    for (int i = 0; i < 4; ++i)
#pragma unroll
        for (int j = 0; j < 4; ++j)
#pragma unroll
            for (int v = 0; v < 4; ++v) acc[i][j][v] = 0.f;

    const int lrow = lane & 15, lcol = lane >> 4;

    for (int kt = 0; kt < NT; ++kt) {
        const int s = kt % 3;
        cp_wait<1>();
        __syncthreads();
        if (kt + 2 < NT) issue_loads(kt + 2, (kt + 2) % 3);
        cp_commit();

#pragma unroll
        for (int ks = 0; ks < 2; ++ks) {
            uint32_t aa[4][4], bb[2][4];
            const uint32_t abase = sbase + s * STAGE_B1
                + (wm * 64 + lrow) * ROWB + ks * 32 + lcol * 16;
#pragma unroll
            for (int mi = 0; mi < 4; ++mi)
                ldsm_x4(aa[mi], abase + mi * 16 * ROWB);
            const uint32_t bbase = sbase + s * STAGE_B1 + TILE_B
                + (wn * 32 + lrow) * ROWB + ks * 32 + lcol * 16;
#pragma unroll
            for (int bj = 0; bj < 2; ++bj)
                ldsm_x4(bb[bj], bbase + bj * 16 * ROWB);
#pragma unroll
            for (int mi = 0; mi < 4; ++mi) {
#pragma unroll
                for (int jn = 0; jn < 4; ++jn) {
                    const int bj = jn >> 1, hf = jn & 1;
                    mma16816h(acc[mi][jn], aa[mi], bb[bj][hf], bb[bj][hf + 2]);
                }
            }
        }
    }

    const int g = lane >> 2, cq = (lane & 3) * 2;
#pragma unroll
    for (int mi = 0; mi < 4; ++mi) {
#pragma unroll
        for (int jn = 0; jn < 4; ++jn) {
            const int r0w = row0 + wm * 64 + mi * 16 + g;
            const int cc = col0 + wn * 32 + jn * 8 + cq;
            *(float2*)(C + (size_t)r0w * N + cc)
                = make_float2(acc[mi][jn][0], acc[mi][jn][1]);
            *(float2*)(C + (size_t)(r0w + 8) * N + cc)
                = make_float2(acc[mi][jn][2], acc[mi][jn][3]);
        }
    }
}

// ---------------------------------------------------------------------------
// Column softmax (axis 0) passes 2 and 3 (pass 1 is fused into scores GEMM)
// ---------------------------------------------------------------------------
__global__ void softmax_pass2() {
    const int j = blockIdx.x * 256 + threadIdx.x;
    float m = -1e30f, s = 0.f;
#pragma unroll 8
    for (int c = 0; c < CHUNKS; ++c) {
        float pm = g_pm[(size_t)c * cNK + j];
        float ps = g_ps[(size_t)c * cNK + j];
        float nm = fmaxf(m, pm);
        s = s * __expf(m - nm) + ps * __expf(pm - nm);
        m = nm;
    }
    g_m[j] = m;
    g_rs[j] = 1.f / s;
}

// Normalize in place + emit single fp16 plane for the fused GEMM.
__global__ void softmax_pass3(float* __restrict__ sc, __half* __restrict__ at) {
    const int j4 = (blockIdx.x * 256 + threadIdx.x) * 4;
    const size_t i = blockIdx.y;
    float4 x = *(float4*)(sc + i * cNK + j4);
    float4 m = *(const float4*)(&g_m[j4]);
    float4 rs = *(const float4*)(&g_rs[j4]);
    x.x = __expf(x.x - m.x) * rs.x;
    x.y = __expf(x.y - m.y) * rs.y;
    x.z = __expf(x.z - m.z) * rs.z;
    x.w = __expf(x.w - m.w) * rs.w;
    *(float4*)(sc + i * cNK + j4) = x;
    __half2 p0 = __floats2half2_rn(x.x, x.y);
    __half2 p1 = __floats2half2_rn(x.z, x.w);
    size_t off = i * cNK + j4;
    *(__half2*)(at + off)     = p0;
    *(__half2*)(at + off + 2) = p1;
}

// ---------------------------------------------------------------------------
// Launch
// ---------------------------------------------------------------------------
extern "C" void kernel_launch(void* const* d_in, const int* in_sizes, int n_in,
                              void* d_out, int out_size)
{
    const float* Xs = (const float*)d_in[0];
    const float* Xk = (const float*)d_in[1];
    const float* Ws = (const float*)d_in[2];
    const float* bs = (const float*)d_in[3];
    const float* Wk = (const float*)d_in[4];
    const float* bk = (const float*)d_in[5];

    float* attns = (float*)d_out;
    float* fused = attns + (size_t)cNS * cNK;

    __nv_bfloat16 *Xsh, *Xsl, *Xkh, *Xkl, *Wsh, *Wsl, *Wkh, *Wkl;
    __nv_bfloat16 *Sh, *Sl, *Kh, *Kl;
    __half *VT, *At;
    cudaGetSymbolAddress((void**)&Xsh, g_Xs_h); cudaGetSymbolAddress((void**)&Xsl, g_Xs_l);
    cudaGetSymbolAddress((void**)&Xkh, g_Xk_h); cudaGetSymbolAddress((void**)&Xkl, g_Xk_l);
    cudaGetSymbolAddress((void**)&Wsh, g_Ws_h); cudaGetSymbolAddress((void**)&Wsl, g_Ws_l);
    cudaGetSymbolAddress((void**)&Wkh, g_Wk_h); cudaGetSymbolAddress((void**)&Wkl, g_Wk_l);
    cudaGetSymbolAddress((void**)&Sh,  g_S_h);  cudaGetSymbolAddress((void**)&Sl,  g_S_l);
    cudaGetSymbolAddress((void**)&Kh,  g_K_h);  cudaGetSymbolAddress((void**)&Kl,  g_K_l);
    cudaGetSymbolAddress((void**)&VT,  g_VT);
    cudaGetSymbolAddress((void**)&At,  g_At);

    cudaFuncSetAttribute(mma_gemm<true, true, false>,
                         cudaFuncAttributeMaxDynamicSharedMemorySize, SMEM_3P);
    cudaFuncSetAttribute(mma_gemm<false, false, true>,
                         cudaFuncAttributeMaxDynamicSharedMemorySize, SMEM_3P);
    cudaFuncSetAttribute(mma_gemm_f16,
                         cudaFuncAttributeMaxDynamicSharedMemorySize, SMEM_1P);

    // Side stream + events for preprocessing overlap (created once on the
    // uncaptured correctness call; replayed identically inside the graph).
    static bool s_init = false;
    static bool s_ok = false;
    static cudaStream_t s_side;
    static cudaEvent_t evFork, evJoin;
    if (!s_init) {
        s_init = true;
        s_ok = (cudaStreamCreateWithFlags(&s_side, cudaStreamNonBlocking) == cudaSuccess)
            && (cudaEventCreateWithFlags(&evFork, cudaEventDisableTiming) == cudaSuccess)
            && (cudaEventCreateWithFlags(&evJoin, cudaEventDisableTiming) == cudaSuccess);
    }
    cudaStream_t sd = s_ok ? s_side : (cudaStream_t)0;

    // Main stream: Xs / Ws splits (feed S-projection)
    {
        size_t n;
        n = (size_t)cNS * cHID; split_kernel<<<(unsigned)(n / 1024), 256>>>(Xs, Xsh, Xsl, n);
        n = (size_t)cHID * cHID; split_kernel<<<(unsigned)(n / 1024), 256>>>(Ws, Wsh, Wsl, n);
    }

    // Side stream: Xk split + V^T (single read of Xk), Wk split
    if (s_ok) {
        cudaEventRecord(evFork, 0);
        cudaStreamWaitEvent(s_side, evFork, 0);
    }
    split_transpose_kernel<<<dim3(cKED / 32, cNK / 32), dim3(32, 8), 0, sd>>>(
        Xk, Xkh, Xkl, VT, cNK, cKED);
    {
        size_t n = (size_t)cHID * cKED;
        split_kernel<<<(unsigned)(n / 1024), 256, 0, sd>>>(Wk, Wkh, Wkl, n);
    }
    if (s_ok) cudaEventRecord(evJoin, s_side);

    // S = Xs @ Ws^T + bs  -> split planes  [8192, 1024]   (overlaps side stream)
    mma_gemm<true, true, false><<<dim3(cHID / 128, cNS / 128), 256, SMEM_3P>>>(
        Xsh, Xsl, Wsh, Wsl, bs, nullptr, Sh, Sl, cNS, cHID, cHID);

    if (s_ok) cudaStreamWaitEvent(0, evJoin, 0);

    // K = Xk @ Wk^T + bk  -> split planes  [8192, 1024]
    mma_gemm<true, true, false><<<dim3(cHID / 128, cNK / 128), 256, SMEM_3P>>>(
        Xkh, Xkl, Wkh, Wkl, bk, nullptr, Kh, Kl, cNK, cHID, cKED);

    // scores = S @ K^T -> fp32 into attns region; epilogue emits softmax
    // chunk stats (pass 1 fused).  chunk == blockIdx.y (128 rows).
    mma_gemm<false, false, true><<<dim3(cNK / 128, cNS / 128), 256, SMEM_3P>>>(
        Sh, Sl, Kh, Kl, nullptr, attns, nullptr, nullptr, cNS, cNK, cHID);

    // softmax passes 2+3 (axis 0), in place; emit fp16 plane
    softmax_pass2<<<cNK / 256, 256>>>();
    softmax_pass3<<<dim3(cNK / 1024, cNS), 256>>>(attns, At);

    // fused = attns @ V = At @ VT^T  [8192, 2048], 1-pass fp16
    mma_gemm_f16<<<dim3(cKED / 128, cNS / 128), 256, SMEM_1P>>>(
        At, VT, fused, cNS, cKED, cNK);
}

// round 8
// speedup vs baseline: 1.7882x; 1.0013x over previous
#include <cuda_runtime.h>
#include <cuda_bf16.h>
#include <cuda_fp16.h>
#include <stdint.h>

// ---------------------------------------------------------------------------
// Problem dims
// ---------------------------------------------------------------------------
static const int cNS  = 8192;
static const int cNK  = 8192;
static const int cHID = 1024;
static const int cKED = 2048;
static const int CHUNKS = 64;  // softmax row chunks = one 128-row CTA tile each

// ---------------------------------------------------------------------------
// Scratch (__device__ globals; allocation-free)
// ---------------------------------------------------------------------------
__device__ __nv_bfloat16 g_Xs_h[(size_t)cNS * cHID];
__device__ __nv_bfloat16 g_Xs_l[(size_t)cNS * cHID];
__device__ __nv_bfloat16 g_Xk_h[(size_t)cNK * cKED];
__device__ __nv_bfloat16 g_Xk_l[(size_t)cNK * cKED];
__device__ __nv_bfloat16 g_Ws_h[(size_t)cHID * cHID];
__device__ __nv_bfloat16 g_Ws_l[(size_t)cHID * cHID];
__device__ __nv_bfloat16 g_Wk_h[(size_t)cHID * cKED];
__device__ __nv_bfloat16 g_Wk_l[(size_t)cHID * cKED];
__device__ __nv_bfloat16 g_S_h[(size_t)cNS * cHID];
__device__ __nv_bfloat16 g_S_l[(size_t)cNS * cHID];
__device__ __nv_bfloat16 g_K_h[(size_t)cNK * cHID];
__device__ __nv_bfloat16 g_K_l[(size_t)cNK * cHID];
__device__ __half g_VT[(size_t)cKED * cNK];            // V^T fp16 [2048, 8192]
__device__ __half g_At[(size_t)cNS * cNK];             // attns fp16 (single plane)
__device__ float g_pm[(size_t)CHUNKS * cNK];
__device__ float g_ps[(size_t)CHUNKS * cNK];
__device__ float g_m[cNK];
__device__ float g_rs[cNK];

// ---------------------------------------------------------------------------
// Helpers
// ---------------------------------------------------------------------------
__device__ __forceinline__ uint32_t smem_to_u32(const void* p) {
    uint32_t a;
    asm("{ .reg .u64 t; cvta.to.shared.u64 t, %1; cvt.u32.u64 %0, t; }"
        : "=r"(a) : "l"(p));
    return a;
}

__device__ __forceinline__ void cp_async16(uint32_t smem_addr, const void* gptr) {
    asm volatile("cp.async.cg.shared.global [%0], [%1], 16;\n"
                 :: "r"(smem_addr), "l"(__cvta_generic_to_global(gptr)));
}
__device__ __forceinline__ void cp_commit() {
    asm volatile("cp.async.commit_group;\n" ::: "memory");
}
template <int N>
__device__ __forceinline__ void cp_wait() {
    asm volatile("cp.async.wait_group %0;\n" :: "n"(N) : "memory");
}

__device__ __forceinline__ void ldsm_x4(uint32_t (&r)[4], uint32_t addr) {
    asm volatile("ldmatrix.sync.aligned.m8n8.x4.shared.b16 {%0,%1,%2,%3}, [%4];\n"
                 : "=r"(r[0]), "=r"(r[1]), "=r"(r[2]), "=r"(r[3]) : "r"(addr));
}

__device__ __forceinline__ void mma16816(float (&c)[4], const uint32_t (&a)[4],
                                         uint32_t b0, uint32_t b1) {
    asm volatile(
        "mma.sync.aligned.m16n8k16.row.col.f32.bf16.bf16.f32 "
        "{%0,%1,%2,%3}, {%4,%5,%6,%7}, {%8,%9}, {%0,%1,%2,%3};\n"
        : "+f"(c[0]), "+f"(c[1]), "+f"(c[2]), "+f"(c[3])
        : "r"(a[0]), "r"(a[1]), "r"(a[2]), "r"(a[3]), "r"(b0), "r"(b1));
}

__device__ __forceinline__ void mma16816h(float (&c)[4], const uint32_t (&a)[4],
                                          uint32_t b0, uint32_t b1) {
    asm volatile(
        "mma.sync.aligned.m16n8k16.row.col.f32.f16.f16.f32 "
        "{%0,%1,%2,%3}, {%4,%5,%6,%7}, {%8,%9}, {%0,%1,%2,%3};\n"
        : "+f"(c[0]), "+f"(c[1]), "+f"(c[2]), "+f"(c[3])
        : "r"(a[0]), "r"(a[1]), "r"(a[2]), "r"(a[3]), "r"(b0), "r"(b1));
}

__device__ __forceinline__ void split1(float x, __nv_bfloat16& h, __nv_bfloat16& l) {
    h = __float2bfloat16(x);
    l = __float2bfloat16(x - __bfloat162float(h));
}

// ---------------------------------------------------------------------------
// Split / fused split+transpose preprocessing
// ---------------------------------------------------------------------------
__global__ void split_kernel(const float* __restrict__ in,
                             __nv_bfloat16* __restrict__ hi,
                             __nv_bfloat16* __restrict__ lo, size_t n) {
    size_t i = ((size_t)blockIdx.x * 256 + threadIdx.x) * 4;
    if (i >= n) return;
    float4 v = *(const float4*)(in + i);
    __nv_bfloat16 h0, h1, h2, h3, l0, l1, l2, l3;
    split1(v.x, h0, l0); split1(v.y, h1, l1);
    split1(v.z, h2, l2); split1(v.w, h3, l3);
    *(__nv_bfloat162*)(hi + i)     = __nv_bfloat162(h0, h1);
    *(__nv_bfloat162*)(hi + i + 2) = __nv_bfloat162(h2, h3);
    *(__nv_bfloat162*)(lo + i)     = __nv_bfloat162(l0, l1);
    *(__nv_bfloat162*)(lo + i + 2) = __nv_bfloat162(l2, l3);
}

// Read Xk once: emit bf16 hi/lo planes (row-major) + fp16 V^T (transposed).
__global__ void split_transpose_kernel(const float* __restrict__ in,
                                       __nv_bfloat16* __restrict__ hi,
                                       __nv_bfloat16* __restrict__ lo,
                                       __half* __restrict__ vt,
                                       int R, int C) {
    __shared__ float t[32][33];
    int c0 = blockIdx.x * 32, r0 = blockIdx.y * 32;
    int tx = threadIdx.x, ty = threadIdx.y;
#pragma unroll
    for (int j = 0; j < 4; ++j) {
        float v = in[(size_t)(r0 + ty + j * 8) * C + c0 + tx];
        t[ty + j * 8][tx] = v;
        __nv_bfloat16 h, l; split1(v, h, l);
        size_t off = (size_t)(r0 + ty + j * 8) * C + c0 + tx;
        hi[off] = h; lo[off] = l;
    }
    __syncthreads();
#pragma unroll
    for (int j = 0; j < 4; ++j)
        vt[(size_t)(c0 + ty + j * 8) * R + r0 + tx] = __float2half(t[tx][ty + j * 8]);
}

// ---------------------------------------------------------------------------
// Common GEMM geometry: 128x128 CTA tile, BK=32, 3-stage cp.async pipeline,
// 8 warps (2x4), warp tile 64x32, 80B-padded SMEM rows (conflict-free ldsm).
// ---------------------------------------------------------------------------
static const int ROWB    = 80;                 // 64B data + 16B pad
static const int TILE_B  = 128 * ROWB;         // 10240 B per plane-tile

// === 3-pass split-bf16 GEMM: C = (Ah+Al) * (Bh+Bl)^T (+bias) ===
// STATS: also emit per-column chunk max/sumexp (softmax pass-1) from registers.
static const int STAGE_B3 = 4 * TILE_B;        // Ah, Al, Bh, Bl
static const int SMEM_3P  = 3 * STAGE_B3;      // 122880

template <bool BIAS, bool SPLIT, bool STATS>
__global__ __launch_bounds__(256, 1)
void mma_gemm(const __nv_bfloat16* __restrict__ Ah, const __nv_bfloat16* __restrict__ Al,
              const __nv_bfloat16* __restrict__ Bh, const __nv_bfloat16* __restrict__ Bl,
              const float* __restrict__ bias,
              float* __restrict__ C,
              __nv_bfloat16* __restrict__ Ch, __nv_bfloat16* __restrict__ Cl,
              int M, int N, int K)
{
    extern __shared__ char sm[];
    const uint32_t sbase = smem_to_u32(sm);

    const int tid = threadIdx.x;
    const int wid = tid >> 5, lane = tid & 31;
    const int wm = wid >> 2, wn = wid & 3;      // 2 x 4 warp grid
    const int row0 = blockIdx.y * 128, col0 = blockIdx.x * 128;

    const __nv_bfloat16* srcs[4] = {
        Ah + (size_t)row0 * K, Al + (size_t)row0 * K,
        Bh + (size_t)col0 * K, Bl + (size_t)col0 * K };

    const int NT = K >> 5;

    auto issue_loads = [&](int kt, int s) {
        const int k0 = kt << 5;
#pragma unroll
        for (int i = 0; i < 8; ++i) {
            int q = tid + i * 256;
            int t = q >> 9, idx = q & 511;
            int row = idx >> 2, c = idx & 3;
            const __nv_bfloat16* g = srcs[t] + (size_t)row * K + k0 + c * 8;
            uint32_t d = sbase + s * STAGE_B3 + t * TILE_B + row * ROWB + c * 16;
            cp_async16(d, g);
        }
    };

    issue_loads(0, 0); cp_commit();
    issue_loads(1, 1); cp_commit();

    float acc[4][4][4];
#pragma unroll
    for (int i = 0; i < 4; ++i)
#pragma unroll
        for (int j = 0; j < 4; ++j)
#pragma unroll
            for (int v = 0; v < 4; ++v) acc[i][j][v] = 0.f;

    const int lrow = lane & 15, lcol = lane >> 4;

    for (int kt = 0; kt < NT; ++kt) {
        const int s = kt % 3;
        cp_wait<1>();
        __syncthreads();
        if (kt + 2 < NT) issue_loads(kt + 2, (kt + 2) % 3);
        cp_commit();

#pragma unroll
        for (int ks = 0; ks < 2; ++ks) {
            uint32_t ah[4][4], al[4][4], bh[2][4], bl[2][4];
            const uint32_t abase = sbase + s * STAGE_B3
                + (wm * 64 + lrow) * ROWB + ks * 32 + lcol * 16;
#pragma unroll
            for (int mi = 0; mi < 4; ++mi) {
                ldsm_x4(ah[mi], abase + mi * 16 * ROWB);
                ldsm_x4(al[mi], abase + mi * 16 * ROWB + TILE_B);
            }
            const uint32_t bbase = sbase + s * STAGE_B3 + 2 * TILE_B
                + (wn * 32 + lrow) * ROWB + ks * 32 + lcol * 16;
#pragma unroll
            for (int bj = 0; bj < 2; ++bj) {
                ldsm_x4(bh[bj], bbase + bj * 16 * ROWB);
                ldsm_x4(bl[bj], bbase + bj * 16 * ROWB + TILE_B);
            }
#pragma unroll
            for (int mi = 0; mi < 4; ++mi) {
#pragma unroll
                for (int jn = 0; jn < 4; ++jn) {
                    const int bj = jn >> 1, hf = jn & 1;
                    mma16816(acc[mi][jn], ah[mi], bh[bj][hf], bh[bj][hf + 2]);
                    mma16816(acc[mi][jn], ah[mi], bl[bj][hf], bl[bj][hf + 2]);
                    mma16816(acc[mi][jn], al[mi], bh[bj][hf], bh[bj][hf + 2]);
                }
            }
        }
    }

    const int g = lane >> 2, cq = (lane & 3) * 2;
#pragma unroll
    for (int mi = 0; mi < 4; ++mi) {
#pragma unroll
        for (int jn = 0; jn < 4; ++jn) {
            const int r0w = row0 + wm * 64 + mi * 16 + g;
            const int cc = col0 + wn * 32 + jn * 8 + cq;
            float v0 = acc[mi][jn][0], v1 = acc[mi][jn][1];
            float v2 = acc[mi][jn][2], v3 = acc[mi][jn][3];
            if (BIAS) {
                float b0 = bias[cc], b1 = bias[cc + 1];
                v0 += b0; v1 += b1; v2 += b0; v3 += b1;
            }
            if (SPLIT) {
                __nv_bfloat16 h0, h1, h2, h3, l0, l1, l2, l3;
                split1(v0, h0, l0); split1(v1, h1, l1);
                split1(v2, h2, l2); split1(v3, h3, l3);
                size_t o0 = (size_t)r0w * N + cc;
                size_t o1 = (size_t)(r0w + 8) * N + cc;
                *(__nv_bfloat162*)(Ch + o0) = __nv_bfloat162(h0, h1);
                *(__nv_bfloat162*)(Cl + o0) = __nv_bfloat162(l0, l1);
                *(__nv_bfloat162*)(Ch + o1) = __nv_bfloat162(h2, h3);
                *(__nv_bfloat162*)(Cl + o1) = __nv_bfloat162(l2, l3);
            } else {
                *(float2*)(C + (size_t)r0w * N + cc)       = make_float2(v0, v1);
                *(float2*)(C + (size_t)(r0w + 8) * N + cc) = make_float2(v2, v3);
            }
        }
    }

    if (STATS) {
        // Softmax pass-1 from registers: per-column max / sumexp over this
        // CTA's 128 rows (chunk == blockIdx.y). Drain cp.async tail before
        // reusing stage smem (outstanding loads may target stage 0).
        cp_wait<0>();
        __syncthreads();
        float* SM_M = (float*)sm;            // [2][128]
        float* SM_S = (float*)(sm + 1024);   // [2][128]
#pragma unroll
        for (int jn = 0; jn < 4; ++jn) {
            float m0 = -1e30f, m1 = -1e30f;
#pragma unroll
            for (int mi = 0; mi < 4; ++mi) {
                m0 = fmaxf(m0, fmaxf(acc[mi][jn][0], acc[mi][jn][2]));
                m1 = fmaxf(m1, fmaxf(acc[mi][jn][1], acc[mi][jn][3]));
            }
            float s0 = 0.f, s1 = 0.f;
#pragma unroll
            for (int mi = 0; mi < 4; ++mi) {
                s0 += __expf(acc[mi][jn][0] - m0) + __expf(acc[mi][jn][2] - m0);
                s1 += __expf(acc[mi][jn][1] - m1) + __expf(acc[mi][jn][3] - m1);
            }
            // reduce across the 8 lanes (stride 4) sharing these two columns
#pragma unroll
            for (int o = 4; o < 32; o <<= 1) {
                float mo = __shfl_xor_sync(0xffffffffu, m0, o);
                float so = __shfl_xor_sync(0xffffffffu, s0, o);
                float nm = fmaxf(m0, mo);
                s0 = s0 * __expf(m0 - nm) + so * __expf(mo - nm); m0 = nm;
                mo = __shfl_xor_sync(0xffffffffu, m1, o);
                so = __shfl_xor_sync(0xffffffffu, s1, o);
                nm = fmaxf(m1, mo);
                s1 = s1 * __expf(m1 - nm) + so * __expf(mo - nm); m1 = nm;
            }
            if ((lane >> 2) == 0) {
                int cit = wn * 32 + jn * 8 + (lane & 3) * 2;
                SM_M[wm * 128 + cit]     = m0;  SM_S[wm * 128 + cit]     = s0;
                SM_M[wm * 128 + cit + 1] = m1;  SM_S[wm * 128 + cit + 1] = s1;
            }
        }
        __syncthreads();
        if (tid < 128) {
            float ma = SM_M[tid], mb = SM_M[128 + tid];
            float sa = SM_S[tid], sb = SM_S[128 + tid];
            float nm = fmaxf(ma, mb);
            float s = sa * __expf(ma - nm) + sb * __expf(mb - nm);
            g_pm[(size_t)blockIdx.y * cNK + col0 + tid] = nm;
            g_ps[(size_t)blockIdx.y * cNK + col0 + tid] = s;
        }
    }
}

// === 1-pass fp16 GEMM: C = A * B^T, fp32 accumulate ===
static const int STAGE_B1 = 2 * TILE_B;        // A, B
static const int SMEM_1P  = 3 * STAGE_B1;      // 61440

__global__ __launch_bounds__(256, 1)
void mma_gemm_f16(const __half* __restrict__ A, const __half* __restrict__ B,
                  float* __restrict__ C, int M, int N, int K)
{
    extern __shared__ char sm[];
    const uint32_t sbase = smem_to_u32(sm);

    const int tid = threadIdx.x;
    const int wid = tid >> 5, lane = tid & 31;
    const int wm = wid >> 2, wn = wid & 3;
    const int row0 = blockIdx.y * 128, col0 = blockIdx.x * 128;

    const __half* srcs[2] = { A + (size_t)row0 * K, B + (size_t)col0 * K };

    const int NT = K >> 5;

    auto issue_loads = [&](int kt, int s) {
        const int k0 = kt << 5;
#pragma unroll
        for (int i = 0; i < 4; ++i) {
            int q = tid + i * 256;
            int t = q >> 9, idx = q & 511;
            int row = idx >> 2, c = idx & 3;
            const __half* g = srcs[t] + (size_t)row * K + k0 + c * 8;
            uint32_t d = sbase + s * STAGE_B1 + t * TILE_B + row * ROWB + c * 16;
            cp_async16(d, g);
        }
    };

    issue_loads(0, 0); cp_commit();
    issue_loads(1, 1); cp_commit();

    float acc[4][4][4];
#pragma unroll
    for (int i = 0; i < 4; ++i)
#pragma unroll
        for (int j = 0; j < 4; ++j)
#pragma unroll
            for (int v = 0; v < 4; ++v) acc[i][j][v] = 0.f;

    const int lrow = lane & 15, lcol = lane >> 4;

    for (int kt = 0; kt < NT; ++kt) {
        const int s = kt % 3;
        cp_wait<1>();
        __syncthreads();
        if (kt + 2 < NT) issue_loads(kt + 2, (kt + 2) % 3);
        cp_commit();

#pragma unroll
        for (int ks = 0; ks < 2; ++ks) {
            uint32_t aa[4][4], bb[2][4];
            const uint32_t abase = sbase + s * STAGE_B1
                + (wm * 64 + lrow) * ROWB + ks * 32 + lcol * 16;
#pragma unroll
            for (int mi = 0; mi < 4; ++mi)
                ldsm_x4(aa[mi], abase + mi * 16 * ROWB);
            const uint32_t bbase = sbase + s * STAGE_B1 + TILE_B
                + (wn * 32 + lrow) * ROWB + ks * 32 + lcol * 16;
#pragma unroll
            for (int bj = 0; bj < 2; ++bj)
                ldsm_x4(bb[bj], bbase + bj * 16 * ROWB);
#pragma unroll
            for (int mi = 0; mi < 4; ++mi) {
#pragma unroll
                for (int jn = 0; jn < 4; ++jn) {
                    const int bj = jn >> 1, hf = jn & 1;
                    mma16816h(acc[mi][jn], aa[mi], bb[bj][hf], bb[bj][hf + 2]);
                }
            }
        }
    }

    const int g = lane >> 2, cq = (lane & 3) * 2;
#pragma unroll
    for (int mi = 0; mi < 4; ++mi) {
#pragma unroll
        for (int jn = 0; jn < 4; ++jn) {
            const int r0w = row0 + wm * 64 + mi * 16 + g;
            const int cc = col0 + wn * 32 + jn * 8 + cq;
            *(float2*)(C + (size_t)r0w * N + cc)
                = make_float2(acc[mi][jn][0], acc[mi][jn][1]);
            *(float2*)(C + (size_t)(r0w + 8) * N + cc)
                = make_float2(acc[mi][jn][2], acc[mi][jn][3]);
        }
    }
}

// ---------------------------------------------------------------------------
// Column softmax (axis 0) passes 2 and 3 (pass 1 is fused into scores GEMM)
// ---------------------------------------------------------------------------
__global__ void softmax_pass2() {
    const int j = blockIdx.x * 256 + threadIdx.x;
    float m = -1e30f, s = 0.f;
#pragma unroll 8
    for (int c = 0; c < CHUNKS; ++c) {
        float pm = g_pm[(size_t)c * cNK + j];
        float ps = g_ps[(size_t)c * cNK + j];
        float nm = fmaxf(m, pm);
        s = s * __expf(m - nm) + ps * __expf(pm - nm);
        m = nm;
    }
    g_m[j] = m;
    g_rs[j] = 1.f / s;
}

// Normalize in place + emit single fp16 plane for the fused GEMM.
__global__ void softmax_pass3(float* __restrict__ sc, __half* __restrict__ at) {
    const int j4 = (blockIdx.x * 256 + threadIdx.x) * 4;
    const size_t i = blockIdx.y;
    float4 x = *(float4*)(sc + i * cNK + j4);
    float4 m = *(const float4*)(&g_m[j4]);
    float4 rs = *(const float4*)(&g_rs[j4]);
    x.x = __expf(x.x - m.x) * rs.x;
    x.y = __expf(x.y - m.y) * rs.y;
    x.z = __expf(x.z - m.z) * rs.z;
    x.w = __expf(x.w - m.w) * rs.w;
    *(float4*)(sc + i * cNK + j4) = x;
    __half2 p0 = __floats2half2_rn(x.x, x.y);
    __half2 p1 = __floats2half2_rn(x.z, x.w);
    size_t off = i * cNK + j4;
    *(__half2*)(at + off)     = p0;
    *(__half2*)(at + off + 2) = p1;
}

// ---------------------------------------------------------------------------
// Launch
// ---------------------------------------------------------------------------
extern "C" void kernel_launch(void* const* d_in, const int* in_sizes, int n_in,
                              void* d_out, int out_size)
{
    const float* Xs = (const float*)d_in[0];
    const float* Xk = (const float*)d_in[1];
    const float* Ws = (const float*)d_in[2];
    const float* bs = (const float*)d_in[3];
    const float* Wk = (const float*)d_in[4];
    const float* bk = (const float*)d_in[5];

    float* attns = (float*)d_out;
    float* fused = attns + (size_t)cNS * cNK;

    __nv_bfloat16 *Xsh, *Xsl, *Xkh, *Xkl, *Wsh, *Wsl, *Wkh, *Wkl;
    __nv_bfloat16 *Sh, *Sl, *Kh, *Kl;
    __half *VT, *At;
    cudaGetSymbolAddress((void**)&Xsh, g_Xs_h); cudaGetSymbolAddress((void**)&Xsl, g_Xs_l);
    cudaGetSymbolAddress((void**)&Xkh, g_Xk_h); cudaGetSymbolAddress((void**)&Xkl, g_Xk_l);
    cudaGetSymbolAddress((void**)&Wsh, g_Ws_h); cudaGetSymbolAddress((void**)&Wsl, g_Ws_l);
    cudaGetSymbolAddress((void**)&Wkh, g_Wk_h); cudaGetSymbolAddress((void**)&Wkl, g_Wk_l);
    cudaGetSymbolAddress((void**)&Sh,  g_S_h);  cudaGetSymbolAddress((void**)&Sl,  g_S_l);
    cudaGetSymbolAddress((void**)&Kh,  g_K_h);  cudaGetSymbolAddress((void**)&Kl,  g_K_l);
    cudaGetSymbolAddress((void**)&VT,  g_VT);
    cudaGetSymbolAddress((void**)&At,  g_At);

    cudaFuncSetAttribute(mma_gemm<true, true, false>,
                         cudaFuncAttributeMaxDynamicSharedMemorySize, SMEM_3P);
    cudaFuncSetAttribute(mma_gemm<false, false, true>,
                         cudaFuncAttributeMaxDynamicSharedMemorySize, SMEM_3P);
    cudaFuncSetAttribute(mma_gemm_f16,
                         cudaFuncAttributeMaxDynamicSharedMemorySize, SMEM_1P);

    // Side stream + events for preprocessing overlap (created once on the
    // uncaptured correctness call; replayed identically inside the graph).
    static bool s_init = false;
    static bool s_ok = false;
    static cudaStream_t s_side;
    static cudaEvent_t evFork, evJoin;
    if (!s_init) {
        s_init = true;
        s_ok = (cudaStreamCreateWithFlags(&s_side, cudaStreamNonBlocking) == cudaSuccess)
            && (cudaEventCreateWithFlags(&evFork, cudaEventDisableTiming) == cudaSuccess)
            && (cudaEventCreateWithFlags(&evJoin, cudaEventDisableTiming) == cudaSuccess);
    }
    cudaStream_t sd = s_ok ? s_side : (cudaStream_t)0;

    // Main stream: Xs / Ws splits (feed S-projection)
    {
        size_t n;
        n = (size_t)cNS * cHID; split_kernel<<<(unsigned)(n / 1024), 256>>>(Xs, Xsh, Xsl, n);
        n = (size_t)cHID * cHID; split_kernel<<<(unsigned)(n / 1024), 256>>>(Ws, Wsh, Wsl, n);
    }

    // Side stream: Xk split + V^T (single read of Xk), Wk split
    if (s_ok) {
        cudaEventRecord(evFork, 0);
        cudaStreamWaitEvent(s_side, evFork, 0);
    }
    split_transpose_kernel<<<dim3(cKED / 32, cNK / 32), dim3(32, 8), 0, sd>>>(
        Xk, Xkh, Xkl, VT, cNK, cKED);
    {
        size_t n = (size_t)cHID * cKED;
        split_kernel<<<(unsigned)(n / 1024), 256, 0, sd>>>(Wk, Wkh, Wkl, n);
    }
    if (s_ok) cudaEventRecord(evJoin, s_side);

    // S = Xs @ Ws^T + bs  -> split planes  [8192, 1024]   (overlaps side stream)
    mma_gemm<true, true, false><<<dim3(cHID / 128, cNS / 128), 256, SMEM_3P>>>(
        Xsh, Xsl, Wsh, Wsl, bs, nullptr, Sh, Sl, cNS, cHID, cHID);

    if (s_ok) cudaStreamWaitEvent(0, evJoin, 0);

    // K = Xk @ Wk^T + bk  -> split planes  [8192, 1024]
    mma_gemm<true, true, false><<<dim3(cHID / 128, cNK / 128), 256, SMEM_3P>>>(
        Xkh, Xkl, Wkh, Wkl, bk, nullptr, Kh, Kl, cNK, cHID, cKED);

    // scores = S @ K^T -> fp32 into attns region; epilogue emits softmax
    // chunk stats (pass 1 fused).  chunk == blockIdx.y (128 rows).
    mma_gemm<false, false, true><<<dim3(cNK / 128, cNS / 128), 256, SMEM_3P>>>(
        Sh, Sl, Kh, Kl, nullptr, attns, nullptr, nullptr, cNS, cNK, cHID);

    // softmax passes 2+3 (axis 0), in place; emit fp16 plane
    softmax_pass2<<<cNK / 256, 256>>>();
    softmax_pass3<<<dim3(cNK / 1024, cNS), 256>>>(attns, At);

    // fused = attns @ V = At @ VT^T  [8192, 2048], 1-pass fp16
    mma_gemm_f16<<<dim3(cKED / 128, cNS / 128), 256, SMEM_1P>>>(
        At, VT, fused, cNS, cKED, cNK);
}

// round 9
// speedup vs baseline: 1.7884x; 1.0001x over previous
#include <cuda_runtime.h>
#include <cuda_bf16.h>
#include <cuda_fp16.h>
#include <stdint.h>

// ---------------------------------------------------------------------------
// Problem dims
// ---------------------------------------------------------------------------
static const int cNS  = 8192;
static const int cNK  = 8192;
static const int cHID = 1024;
static const int cKED = 2048;
static const int CHUNKS = 64;  // softmax row chunks = one 128-row CTA tile each

// ---------------------------------------------------------------------------
// Scratch (__device__ globals; allocation-free)
// ---------------------------------------------------------------------------
__device__ __nv_bfloat16 g_Xs_h[(size_t)cNS * cHID];
__device__ __nv_bfloat16 g_Xs_l[(size_t)cNS * cHID];
__device__ __nv_bfloat16 g_Xk_h[(size_t)cNK * cKED];
__device__ __nv_bfloat16 g_Xk_l[(size_t)cNK * cKED];
__device__ __nv_bfloat16 g_Ws_h[(size_t)cHID * cHID];
__device__ __nv_bfloat16 g_Ws_l[(size_t)cHID * cHID];
__device__ __nv_bfloat16 g_Wk_h[(size_t)cHID * cKED];
__device__ __nv_bfloat16 g_Wk_l[(size_t)cHID * cKED];
__device__ __nv_bfloat16 g_S_h[(size_t)cNS * cHID];
__device__ __nv_bfloat16 g_S_l[(size_t)cNS * cHID];
__device__ __nv_bfloat16 g_K_h[(size_t)cNK * cHID];
__device__ __nv_bfloat16 g_K_l[(size_t)cNK * cHID];
__device__ __half g_VT[(size_t)cKED * cNK];            // V^T fp16 [2048, 8192]
__device__ __half g_At[(size_t)cNS * cNK];             // attns fp16 (single plane)
__device__ float g_pm[(size_t)CHUNKS * cNK];
__device__ float g_ps[(size_t)CHUNKS * cNK];
__device__ float g_m[cNK];
__device__ float g_rs[cNK];

// ---------------------------------------------------------------------------
// Helpers
// ---------------------------------------------------------------------------
__device__ __forceinline__ uint32_t smem_to_u32(const void* p) {
    uint32_t a;
    asm("{ .reg .u64 t; cvta.to.shared.u64 t, %1; cvt.u32.u64 %0, t; }"
        : "=r"(a) : "l"(p));
    return a;
}

__device__ __forceinline__ void cp_async16(uint32_t smem_addr, const void* gptr) {
    asm volatile("cp.async.cg.shared.global [%0], [%1], 16;\n"
                 :: "r"(smem_addr), "l"(__cvta_generic_to_global(gptr)));
}
__device__ __forceinline__ void cp_commit() {
    asm volatile("cp.async.commit_group;\n" ::: "memory");
}
template <int N>
__device__ __forceinline__ void cp_wait() {
    asm volatile("cp.async.wait_group %0;\n" :: "n"(N) : "memory");
}

__device__ __forceinline__ void ldsm_x4(uint32_t (&r)[4], uint32_t addr) {
    asm volatile("ldmatrix.sync.aligned.m8n8.x4.shared.b16 {%0,%1,%2,%3}, [%4];\n"
                 : "=r"(r[0]), "=r"(r[1]), "=r"(r[2]), "=r"(r[3]) : "r"(addr));
}

__device__ __forceinline__ void mma16816(float (&c)[4], const uint32_t (&a)[4],
                                         uint32_t b0, uint32_t b1) {
    asm volatile(
        "mma.sync.aligned.m16n8k16.row.col.f32.bf16.bf16.f32 "
        "{%0,%1,%2,%3}, {%4,%5,%6,%7}, {%8,%9}, {%0,%1,%2,%3};\n"
        : "+f"(c[0]), "+f"(c[1]), "+f"(c[2]), "+f"(c[3])
        : "r"(a[0]), "r"(a[1]), "r"(a[2]), "r"(a[3]), "r"(b0), "r"(b1));
}

__device__ __forceinline__ void mma16816h(float (&c)[4], const uint32_t (&a)[4],
                                          uint32_t b0, uint32_t b1) {
    asm volatile(
        "mma.sync.aligned.m16n8k16.row.col.f32.f16.f16.f32 "
        "{%0,%1,%2,%3}, {%4,%5,%6,%7}, {%8,%9}, {%0,%1,%2,%3};\n"
        : "+f"(c[0]), "+f"(c[1]), "+f"(c[2]), "+f"(c[3])
        : "r"(a[0]), "r"(a[1]), "r"(a[2]), "r"(a[3]), "r"(b0), "r"(b1));
}

__device__ __forceinline__ void split1(float x, __nv_bfloat16& h, __nv_bfloat16& l) {
    h = __float2bfloat16(x);
    l = __float2bfloat16(x - __bfloat162float(h));
}

// ---------------------------------------------------------------------------
// Split / fused split+transpose preprocessing
// ---------------------------------------------------------------------------
__global__ void split_kernel(const float* __restrict__ in,
                             __nv_bfloat16* __restrict__ hi,
                             __nv_bfloat16* __restrict__ lo, size_t n) {
    size_t i = ((size_t)blockIdx.x * 256 + threadIdx.x) * 4;
    if (i >= n) return;
    float4 v = *(const float4*)(in + i);
    __nv_bfloat16 h0, h1, h2, h3, l0, l1, l2, l3;
    split1(v.x, h0, l0); split1(v.y, h1, l1);
    split1(v.z, h2, l2); split1(v.w, h3, l3);
    *(__nv_bfloat162*)(hi + i)     = __nv_bfloat162(h0, h1);
    *(__nv_bfloat162*)(hi + i + 2) = __nv_bfloat162(h2, h3);
    *(__nv_bfloat162*)(lo + i)     = __nv_bfloat162(l0, l1);
    *(__nv_bfloat162*)(lo + i + 2) = __nv_bfloat162(l2, l3);
}

// Read Xk once: emit bf16 hi/lo planes (row-major) + fp16 V^T (transposed).
__global__ void split_transpose_kernel(const float* __restrict__ in,
                                       __nv_bfloat16* __restrict__ hi,
                                       __nv_bfloat16* __restrict__ lo,
                                       __half* __restrict__ vt,
                                       int R, int C) {
    __shared__ float t[32][33];
    int c0 = blockIdx.x * 32, r0 = blockIdx.y * 32;
    int tx = threadIdx.x, ty = threadIdx.y;
#pragma unroll
    for (int j = 0; j < 4; ++j) {
        float v = in[(size_t)(r0 + ty + j * 8) * C + c0 + tx];
        t[ty + j * 8][tx] = v;
        __nv_bfloat16 h, l; split1(v, h, l);
        size_t off = (size_t)(r0 + ty + j * 8) * C + c0 + tx;
        hi[off] = h; lo[off] = l;
    }
    __syncthreads();
#pragma unroll
    for (int j = 0; j < 4; ++j)
        vt[(size_t)(c0 + ty + j * 8) * R + r0 + tx] = __float2half(t[tx][ty + j * 8]);
}

// ---------------------------------------------------------------------------
// Common GEMM geometry: 128x128 CTA tile, BK=32, 3-stage cp.async pipeline,
// 8 warps (2x4), warp tile 64x32, 80B-padded SMEM rows (conflict-free ldsm).
// ---------------------------------------------------------------------------
static const int ROWB    = 80;                 // 64B data + 16B pad
static const int TILE_B  = 128 * ROWB;         // 10240 B per plane-tile

// === 3-pass split-bf16 GEMM: C = (Ah+Al) * (Bh+Bl)^T (+bias) ===
// STATS: also emit per-column chunk max/sumexp (softmax pass-1) from registers.
static const int STAGE_B3 = 4 * TILE_B;        // Ah, Al, Bh, Bl
static const int SMEM_3P  = 3 * STAGE_B3;      // 122880

template <bool BIAS, bool SPLIT, bool STATS>
__global__ __launch_bounds__(256, 1)
void mma_gemm(const __nv_bfloat16* __restrict__ Ah, const __nv_bfloat16* __restrict__ Al,
              const __nv_bfloat16* __restrict__ Bh, const __nv_bfloat16* __restrict__ Bl,
              const float* __restrict__ bias,
              float* __restrict__ C,
              __nv_bfloat16* __restrict__ Ch, __nv_bfloat16* __restrict__ Cl,
              int M, int N, int K)
{
    extern __shared__ char sm[];
    const uint32_t sbase = smem_to_u32(sm);

    const int tid = threadIdx.x;
    const int wid = tid >> 5, lane = tid & 31;
    const int wm = wid >> 2, wn = wid & 3;      // 2 x 4 warp grid
    const int row0 = blockIdx.y * 128, col0 = blockIdx.x * 128;

    const __nv_bfloat16* srcs[4] = {
        Ah + (size_t)row0 * K, Al + (size_t)row0 * K,
        Bh + (size_t)col0 * K, Bl + (size_t)col0 * K };

    const int NT = K >> 5;

    auto issue_loads = [&](int kt, int s) {
        const int k0 = kt << 5;
#pragma unroll
        for (int i = 0; i < 8; ++i) {
            int q = tid + i * 256;
            int t = q >> 9, idx = q & 511;
            int row = idx >> 2, c = idx & 3;
            const __nv_bfloat16* g = srcs[t] + (size_t)row * K + k0 + c * 8;
            uint32_t d = sbase + s * STAGE_B3 + t * TILE_B + row * ROWB + c * 16;
            cp_async16(d, g);
        }
    };

    issue_loads(0, 0); cp_commit();
    issue_loads(1, 1); cp_commit();

    float acc[4][4][4];
#pragma unroll
    for (int i = 0; i < 4; ++i)
#pragma unroll
        for (int j = 0; j < 4; ++j)
#pragma unroll
            for (int v = 0; v < 4; ++v) acc[i][j][v] = 0.f;

    const int lrow = lane & 15, lcol = lane >> 4;

    for (int kt = 0; kt < NT; ++kt) {
        const int s = kt % 3;
        cp_wait<1>();
        __syncthreads();
        if (kt + 2 < NT) issue_loads(kt + 2, (kt + 2) % 3);
        cp_commit();

#pragma unroll
        for (int ks = 0; ks < 2; ++ks) {
            uint32_t ah[4][4], al[4][4], bh[2][4], bl[2][4];
            const uint32_t abase = sbase + s * STAGE_B3
                + (wm * 64 + lrow) * ROWB + ks * 32 + lcol * 16;
#pragma unroll
            for (int mi = 0; mi < 4; ++mi) {
                ldsm_x4(ah[mi], abase + mi * 16 * ROWB);
                ldsm_x4(al[mi], abase + mi * 16 * ROWB + TILE_B);
            }
            const uint32_t bbase = sbase + s * STAGE_B3 + 2 * TILE_B
                + (wn * 32 + lrow) * ROWB + ks * 32 + lcol * 16;
#pragma unroll
            for (int bj = 0; bj < 2; ++bj) {
                ldsm_x4(bh[bj], bbase + bj * 16 * ROWB);
                ldsm_x4(bl[bj], bbase + bj * 16 * ROWB + TILE_B);
            }
#pragma unroll
            for (int mi = 0; mi < 4; ++mi) {
#pragma unroll
                for (int jn = 0; jn < 4; ++jn) {
                    const int bj = jn >> 1, hf = jn & 1;
                    mma16816(acc[mi][jn], ah[mi], bh[bj][hf], bh[bj][hf + 2]);
                    mma16816(acc[mi][jn], ah[mi], bl[bj][hf], bl[bj][hf + 2]);
                    mma16816(acc[mi][jn], al[mi], bh[bj][hf], bh[bj][hf + 2]);
                }
            }
        }
    }

    const int g = lane >> 2, cq = (lane & 3) * 2;
#pragma unroll
    for (int mi = 0; mi < 4; ++mi) {
#pragma unroll
        for (int jn = 0; jn < 4; ++jn) {
            const int r0w = row0 + wm * 64 + mi * 16 + g;
            const int cc = col0 + wn * 32 + jn * 8 + cq;
            float v0 = acc[mi][jn][0], v1 = acc[mi][jn][1];
            float v2 = acc[mi][jn][2], v3 = acc[mi][jn][3];
            if (BIAS) {
                float b0 = bias[cc], b1 = bias[cc + 1];
                v0 += b0; v1 += b1; v2 += b0; v3 += b1;
            }
            if (SPLIT) {
                __nv_bfloat16 h0, h1, h2, h3, l0, l1, l2, l3;
                split1(v0, h0, l0); split1(v1, h1, l1);
                split1(v2, h2, l2); split1(v3, h3, l3);
                size_t o0 = (size_t)r0w * N + cc;
                size_t o1 = (size_t)(r0w + 8) * N + cc;
                *(__nv_bfloat162*)(Ch + o0) = __nv_bfloat162(h0, h1);
                *(__nv_bfloat162*)(Cl + o0) = __nv_bfloat162(l0, l1);
                *(__nv_bfloat162*)(Ch + o1) = __nv_bfloat162(h2, h3);
                *(__nv_bfloat162*)(Cl + o1) = __nv_bfloat162(l2, l3);
            } else {
                *(float2*)(C + (size_t)r0w * N + cc)       = make_float2(v0, v1);
                *(float2*)(C + (size_t)(r0w + 8) * N + cc) = make_float2(v2, v3);
            }
        }
    }

    if (STATS) {
        // Softmax pass-1 from registers: per-column max / sumexp over this
        // CTA's 128 rows (chunk == blockIdx.y). Drain cp.async tail before
        // reusing stage smem (outstanding loads may target stage 0).
        cp_wait<0>();
        __syncthreads();
        float* SM_M = (float*)sm;            // [2][128]
        float* SM_S = (float*)(sm + 1024);   // [2][128]
#pragma unroll
        for (int jn = 0; jn < 4; ++jn) {
            float m0 = -1e30f, m1 = -1e30f;
#pragma unroll
            for (int mi = 0; mi < 4; ++mi) {
                m0 = fmaxf(m0, fmaxf(acc[mi][jn][0], acc[mi][jn][2]));
                m1 = fmaxf(m1, fmaxf(acc[mi][jn][1], acc[mi][jn][3]));
            }
            float s0 = 0.f, s1 = 0.f;
#pragma unroll
            for (int mi = 0; mi < 4; ++mi) {
                s0 += __expf(acc[mi][jn][0] - m0) + __expf(acc[mi][jn][2] - m0);
                s1 += __expf(acc[mi][jn][1] - m1) + __expf(acc[mi][jn][3] - m1);
            }
            // reduce across the 8 lanes (stride 4) sharing these two columns
#pragma unroll
            for (int o = 4; o < 32; o <<= 1) {
                float mo = __shfl_xor_sync(0xffffffffu, m0, o);
                float so = __shfl_xor_sync(0xffffffffu, s0, o);
                float nm = fmaxf(m0, mo);
                s0 = s0 * __expf(m0 - nm) + so * __expf(mo - nm); m0 = nm;
                mo = __shfl_xor_sync(0xffffffffu, m1, o);
                so = __shfl_xor_sync(0xffffffffu, s1, o);
                nm = fmaxf(m1, mo);
                s1 = s1 * __expf(m1 - nm) + so * __expf(mo - nm); m1 = nm;
            }
            if ((lane >> 2) == 0) {
                int cit = wn * 32 + jn * 8 + (lane & 3) * 2;
                SM_M[wm * 128 + cit]     = m0;  SM_S[wm * 128 + cit]     = s0;
                SM_M[wm * 128 + cit + 1] = m1;  SM_S[wm * 128 + cit + 1] = s1;
            }
        }
        __syncthreads();
        if (tid < 128) {
            float ma = SM_M[tid], mb = SM_M[128 + tid];
            float sa = SM_S[tid], sb = SM_S[128 + tid];
            float nm = fmaxf(ma, mb);
            float s = sa * __expf(ma - nm) + sb * __expf(mb - nm);
            g_pm[(size_t)blockIdx.y * cNK + col0 + tid] = nm;
            g_ps[(size_t)blockIdx.y * cNK + col0 + tid] = s;
        }
    }
}

// === 1-pass fp16 GEMM: C = A * B^T, fp32 accumulate ===
static const int STAGE_B1 = 2 * TILE_B;        // A, B
static const int SMEM_1P  = 3 * STAGE_B1;      // 61440

__global__ __launch_bounds__(256, 1)
void mma_gemm_f16(const __half* __restrict__ A, const __half* __restrict__ B,
                  float* __restrict__ C, int M, int N, int K)
{
    extern __shared__ char sm[];
    const uint32_t sbase = smem_to_u32(sm);

    const int tid = threadIdx.x;
    const int wid = tid >> 5, lane = tid & 31;
    const int wm = wid >> 2, wn = wid & 3;
    const int row0 = blockIdx.y * 128, col0 = blockIdx.x * 128;

    const __half* srcs[2] = { A + (size_t)row0 * K, B + (size_t)col0 * K };

    const int NT = K >> 5;

    auto issue_loads = [&](int kt, int s) {
        const int k0 = kt << 5;
#pragma unroll
        for (int i = 0; i < 4; ++i) {
            int q = tid + i * 256;
            int t = q >> 9, idx = q & 511;
            int row = idx >> 2, c = idx & 3;
            const __half* g = srcs[t] + (size_t)row * K + k0 + c * 8;
            uint32_t d = sbase + s * STAGE_B1 + t * TILE_B + row * ROWB + c * 16;
            cp_async16(d, g);
        }
    };

    issue_loads(0, 0); cp_commit();
    issue_loads(1, 1); cp_commit();

    float acc[4][4][4];
#pragma unroll
    for (int i = 0; i < 4; ++i)
#pragma unroll
        for (int j = 0; j < 4; ++j)
#pragma unroll
            for (int v = 0; v < 4; ++v) acc[i][j][v] = 0.f;

    const int lrow = lane & 15, lcol = lane >> 4;

    for (int kt = 0; kt < NT; ++kt) {
        const int s = kt % 3;
        cp_wait<1>();
        __syncthreads();
        if (kt + 2 < NT) issue_loads(kt + 2, (kt + 2) % 3);
        cp_commit();

#pragma unroll
        for (int ks = 0; ks < 2; ++ks) {
            uint32_t aa[4][4], bb[2][4];
            const uint32_t abase = sbase + s * STAGE_B1
                + (wm * 64 + lrow) * ROWB + ks * 32 + lcol * 16;
#pragma unroll
            for (int mi = 0; mi < 4; ++mi)
                ldsm_x4(aa[mi], abase + mi * 16 * ROWB);
            const uint32_t bbase = sbase + s * STAGE_B1 + TILE_B
                + (wn * 32 + lrow) * ROWB + ks * 32 + lcol * 16;
#pragma unroll
            for (int bj = 0; bj < 2; ++bj)
                ldsm_x4(bb[bj], bbase + bj * 16 * ROWB);
#pragma unroll
            for (int mi = 0; mi < 4; ++mi) {
#pragma unroll
                for (int jn = 0; jn < 4; ++jn) {
                    const int bj = jn >> 1, hf = jn & 1;
                    mma16816h(acc[mi][jn], aa[mi], bb[bj][hf], bb[bj][hf + 2]);
                }
            }
        }
    }

    const int g = lane >> 2, cq = (lane & 3) * 2;
#pragma unroll
    for (int mi = 0; mi < 4; ++mi) {
#pragma unroll
        for (int jn = 0; jn < 4; ++jn) {
            const int r0w = row0 + wm * 64 + mi * 16 + g;
            const int cc = col0 + wn * 32 + jn * 8 + cq;
            *(float2*)(C + (size_t)r0w * N + cc)
                = make_float2(acc[mi][jn][0], acc[mi][jn][1]);
            *(float2*)(C + (size_t)(r0w + 8) * N + cc)
                = make_float2(acc[mi][jn][2], acc[mi][jn][3]);
        }
    }
}

// ---------------------------------------------------------------------------
// Column softmax (axis 0): pass 1 fused into scores GEMM; pass 2 reduces
// chunk stats; pass 3 is split into a critical-path fp16 emit (3a) and an
// off-critical-path fp32 in-place normalize (3b, overlapped with fused GEMM).
// ---------------------------------------------------------------------------
__global__ void softmax_pass2() {
    const int j = blockIdx.x * 256 + threadIdx.x;
    float m = -1e30f, s = 0.f;
#pragma unroll 8
    for (int c = 0; c < CHUNKS; ++c) {
        float pm = g_pm[(size_t)c * cNK + j];
        float ps = g_ps[(size_t)c * cNK + j];
        float nm = fmaxf(m, pm);
        s = s * __expf(m - nm) + ps * __expf(pm - nm);
        m = nm;
    }
    g_m[j] = m;
    g_rs[j] = 1.f / s;
}

// 3a: read raw scores, emit fp16 attns plane only (feeds fused GEMM).
__global__ void softmax_emit_f16(const float* __restrict__ sc,
                                 __half* __restrict__ at) {
    const int j4 = (blockIdx.x * 256 + threadIdx.x) * 4;
    const size_t i = blockIdx.y;
    float4 x = *(const float4*)(sc + i * cNK + j4);
    float4 m = *(const float4*)(&g_m[j4]);
    float4 rs = *(const float4*)(&g_rs[j4]);
    float e0 = __expf(x.x - m.x) * rs.x;
    float e1 = __expf(x.y - m.y) * rs.y;
    float e2 = __expf(x.z - m.z) * rs.z;
    float e3 = __expf(x.w - m.w) * rs.w;
    size_t off = i * cNK + j4;
    *(__half2*)(at + off)     = __floats2half2_rn(e0, e1);
    *(__half2*)(at + off + 2) = __floats2half2_rn(e2, e3);
}

// 3b: read raw scores, normalize fp32 attns in place (runs concurrent with
// the fused GEMM on a side stream; touches only the attns region).
__global__ void softmax_norm_f32(float* __restrict__ sc) {
    const int j4 = (blockIdx.x * 256 + threadIdx.x) * 4;
    const size_t i = blockIdx.y;
    float4 x = *(float4*)(sc + i * cNK + j4);
    float4 m = *(const float4*)(&g_m[j4]);
    float4 rs = *(const float4*)(&g_rs[j4]);
    x.x = __expf(x.x - m.x) * rs.x;
    x.y = __expf(x.y - m.y) * rs.y;
    x.z = __expf(x.z - m.z) * rs.z;
    x.w = __expf(x.w - m.w) * rs.w;
    *(float4*)(sc + i * cNK + j4) = x;
}

// ---------------------------------------------------------------------------
// Launch
// ---------------------------------------------------------------------------
extern "C" void kernel_launch(void* const* d_in, const int* in_sizes, int n_in,
                              void* d_out, int out_size)
{
    const float* Xs = (const float*)d_in[0];
    const float* Xk = (const float*)d_in[1];
    const float* Ws = (const float*)d_in[2];
    const float* bs = (const float*)d_in[3];
    const float* Wk = (const float*)d_in[4];
    const float* bk = (const float*)d_in[5];

    float* attns = (float*)d_out;
    float* fused = attns + (size_t)cNS * cNK;

    __nv_bfloat16 *Xsh, *Xsl, *Xkh, *Xkl, *Wsh, *Wsl, *Wkh, *Wkl;
    __nv_bfloat16 *Sh, *Sl, *Kh, *Kl;
    __half *VT, *At;
    cudaGetSymbolAddress((void**)&Xsh, g_Xs_h); cudaGetSymbolAddress((void**)&Xsl, g_Xs_l);
    cudaGetSymbolAddress((void**)&Xkh, g_Xk_h); cudaGetSymbolAddress((void**)&Xkl, g_Xk_l);
    cudaGetSymbolAddress((void**)&Wsh, g_Ws_h); cudaGetSymbolAddress((void**)&Wsl, g_Ws_l);
    cudaGetSymbolAddress((void**)&Wkh, g_Wk_h); cudaGetSymbolAddress((void**)&Wkl, g_Wk_l);
    cudaGetSymbolAddress((void**)&Sh,  g_S_h);  cudaGetSymbolAddress((void**)&Sl,  g_S_l);
    cudaGetSymbolAddress((void**)&Kh,  g_K_h);  cudaGetSymbolAddress((void**)&Kl,  g_K_l);
    cudaGetSymbolAddress((void**)&VT,  g_VT);
    cudaGetSymbolAddress((void**)&At,  g_At);

    cudaFuncSetAttribute(mma_gemm<true, true, false>,
                         cudaFuncAttributeMaxDynamicSharedMemorySize, SMEM_3P);
    cudaFuncSetAttribute(mma_gemm<false, false, true>,
                         cudaFuncAttributeMaxDynamicSharedMemorySize, SMEM_3P);
    cudaFuncSetAttribute(mma_gemm_f16,
                         cudaFuncAttributeMaxDynamicSharedMemorySize, SMEM_1P);

    // Side stream + events (created once on the uncaptured correctness call;
    // the fork/join pattern is graph-capture legal — proven in R8).
    static bool s_init = false;
    static bool s_ok = false;
    static cudaStream_t s_side;
    static cudaEvent_t evFork, evJoin, evFork2, evJoin2;
    if (!s_init) {
        s_init = true;
        s_ok = (cudaStreamCreateWithFlags(&s_side, cudaStreamNonBlocking) == cudaSuccess)
            && (cudaEventCreateWithFlags(&evFork,  cudaEventDisableTiming) == cudaSuccess)
            && (cudaEventCreateWithFlags(&evJoin,  cudaEventDisableTiming) == cudaSuccess)
            && (cudaEventCreateWithFlags(&evFork2, cudaEventDisableTiming) == cudaSuccess)
            && (cudaEventCreateWithFlags(&evJoin2, cudaEventDisableTiming) == cudaSuccess);
    }
    cudaStream_t sd = s_ok ? s_side : (cudaStream_t)0;

    // Main stream: Xs / Ws splits (feed S-projection)
    {
        size_t n;
        n = (size_t)cNS * cHID; split_kernel<<<(unsigned)(n / 1024), 256>>>(Xs, Xsh, Xsl, n);
        n = (size_t)cHID * cHID; split_kernel<<<(unsigned)(n / 1024), 256>>>(Ws, Wsh, Wsl, n);
    }

    // Side stream: Xk split + V^T (single read of Xk), Wk split, K-projection.
    if (s_ok) {
        cudaEventRecord(evFork, 0);
        cudaStreamWaitEvent(s_side, evFork, 0);
    }
    split_transpose_kernel<<<dim3(cKED / 32, cNK / 32), dim3(32, 8), 0, sd>>>(
        Xk, Xkh, Xkl, VT, cNK, cKED);
    {
        size_t n = (size_t)cHID * cKED;
        split_kernel<<<(unsigned)(n / 1024), 256, 0, sd>>>(Wk, Wkh, Wkl, n);
    }
    // K = Xk @ Wk^T + bk  -> split planes  [8192, 1024]  (side stream,
    // concurrent with S-projection on main — fills wave-quantization tails)
    mma_gemm<true, true, false><<<dim3(cHID / 128, cNK / 128), 256, SMEM_3P, sd>>>(
        Xkh, Xkl, Wkh, Wkl, bk, nullptr, Kh, Kl, cNK, cHID, cKED);
    if (s_ok) cudaEventRecord(evJoin, s_side);

    // S = Xs @ Ws^T + bs  -> split planes  [8192, 1024]   (main stream)
    mma_gemm<true, true, false><<<dim3(cHID / 128, cNS / 128), 256, SMEM_3P>>>(
        Xsh, Xsl, Wsh, Wsl, bs, nullptr, Sh, Sl, cNS, cHID, cHID);

    if (s_ok) cudaStreamWaitEvent(0, evJoin, 0);

    // scores = S @ K^T -> fp32 into attns region; epilogue emits softmax
    // chunk stats (pass 1 fused).  chunk == blockIdx.y (128 rows).
    mma_gemm<false, false, true><<<dim3(cNK / 128, cNS / 128), 256, SMEM_3P>>>(
        Sh, Sl, Kh, Kl, nullptr, attns, nullptr, nullptr, cNS, cNK, cHID);

    // pass 2 (global stats) + pass 3a (fp16 emit — critical path)
    softmax_pass2<<<cNK / 256, 256>>>();
    softmax_emit_f16<<<dim3(cNK / 1024, cNS), 256>>>(attns, At);

    // pass 3b (fp32 normalize in place) overlaps with the fused GEMM.
    if (s_ok) {
        cudaEventRecord(evFork2, 0);
        cudaStreamWaitEvent(s_side, evFork2, 0);
        softmax_norm_f32<<<dim3(cNK / 1024, cNS), 256, 0, s_side>>>(attns);
        cudaEventRecord(evJoin2, s_side);
    } else {
        softmax_norm_f32<<<dim3(cNK / 1024, cNS), 256>>>(attns);
    }

    // fused = attns @ V = At @ VT^T  [8192, 2048], 1-pass fp16  (main stream)
    mma_gemm_f16<<<dim3(cKED / 128, cNS / 128), 256, SMEM_1P>>>(
        At, VT, fused, cNS, cKED, cNK);

    // Join side stream so the captured graph is well-formed.
    if (s_ok) cudaStreamWaitEvent(0, evJoin2, 0);
}